// round 11
// baseline (speedup 1.0000x reference)
#include <cuda_runtime.h>
#include <math.h>
#include <stdint.h>

// Problem constants
#define Bb   16
#define NPp  512
#define Nn   1024
#define Cc   1024
#define Hh   16
#define HDd  64
#define C3   3072
#define HIDh 4096
#define Mtok 8192   // B*NP

// ---------------- scratch (device globals) ----------------
__device__ float g_h   [(size_t)Mtok * Cc];
__device__ float g_qkv [(size_t)Mtok * C3];
__device__ float g_kf  [(size_t)Bb * Hh * Nn * HDd];
__device__ float g_vf  [(size_t)Bb * Hh * Nn * HDd];
__device__ float g_o   [(size_t)Mtok * Cc];
__device__ float g_x1  [(size_t)Mtok * Cc];
__device__ float g_hid [(size_t)Mtok * HIDh];
__device__ int   g_p2t [Bb * Nn];
// tf32-rounded weights
__device__ float g_wq  [(size_t)Cc * C3];
__device__ float g_wp  [(size_t)Cc * Cc];
__device__ float g_w1  [(size_t)Cc * HIDh];
__device__ float g_w2  [(size_t)HIDh * Cc];

// ---------------- helpers ----------------
__device__ __forceinline__ uint32_t f2tf32(float f) {
    uint32_t u;
    asm("cvt.rna.tf32.f32 %0, %1;" : "=r"(u) : "f"(f));
    return u;
}
__device__ __forceinline__ float rnd32(float f) { return __uint_as_float(f2tf32(f)); }

__device__ __forceinline__ void mma_tf32(float c[4], const uint32_t a[4], const uint32_t b[2]) {
    asm volatile(
        "mma.sync.aligned.m16n8k8.row.col.f32.tf32.tf32.f32 "
        "{%0,%1,%2,%3}, {%4,%5,%6,%7}, {%8,%9}, {%0,%1,%2,%3};"
        : "+f"(c[0]), "+f"(c[1]), "+f"(c[2]), "+f"(c[3])
        : "r"(a[0]), "r"(a[1]), "r"(a[2]), "r"(a[3]), "r"(b[0]), "r"(b[1]));
}
__device__ __forceinline__ void ldsm_x4(uint32_t a[4], uint32_t saddr) {
    asm volatile("ldmatrix.sync.aligned.m8n8.x4.shared.b16 {%0,%1,%2,%3}, [%4];"
                 : "=r"(a[0]), "=r"(a[1]), "=r"(a[2]), "=r"(a[3]) : "r"(saddr));
}
__device__ __forceinline__ void cp16(uint32_t saddr, const void* g) {
    asm volatile("cp.async.cg.shared.global [%0], [%1], 16;" :: "r"(saddr), "l"(g));
}
#define CP_COMMIT() asm volatile("cp.async.commit_group;")
#define CP_WAIT(n)  asm volatile("cp.async.wait_group %0;" :: "n"(n))

// ---------------- weight pre-round: all four weights in one launch ----------------
__global__ void round_all_kernel(const float4* __restrict__ wq_in, const float4* __restrict__ wp_in,
                                 const float4* __restrict__ w1_in, const float4* __restrict__ w2_in)
{
    const size_t NQ = (size_t)Cc * C3 / 4;
    const size_t NP_ = (size_t)Cc * Cc / 4;
    const size_t N1 = (size_t)Cc * HIDh / 4;
    const size_t N2 = (size_t)HIDh * Cc / 4;
    size_t i = (size_t)blockIdx.x * blockDim.x + threadIdx.x;
    const float4* src; float4* dst; size_t off;
    if (i < NQ)                    { src = wq_in; dst = (float4*)g_wq; off = i; }
    else if (i < NQ + NP_)         { src = wp_in; dst = (float4*)g_wp; off = i - NQ; }
    else if (i < NQ + NP_ + N1)    { src = w1_in; dst = (float4*)g_w1; off = i - NQ - NP_; }
    else if (i < NQ + NP_ + N1+N2) { src = w2_in; dst = (float4*)g_w2; off = i - NQ - NP_ - N1; }
    else return;
    float4 v = src[off];
    v.x = rnd32(v.x); v.y = rnd32(v.y); v.z = rnd32(v.z); v.w = rnd32(v.w);
    dst[off] = v;
}

// ---------------- tf32 mma.sync GEMM, cp.async 3-stage, BK=32, ldsm A-frags ----------------
// C[M,N] = act(A @ B + bias) + resid ;  A:[M,K] row-major, B:[K,N] row-major.
// BM=128, BN=128, BK=32; 256 thr = 8 warps, warp tile 64x32. 2 blocks/SM (16 warps).
template<bool HAS_BIAS, bool GELU_ACT, bool HAS_RES, bool ROUND_OUT>
__global__ void __launch_bounds__(256) mma_gemm(
    const float* __restrict__ A, const float* __restrict__ Bm, float* __restrict__ Cm,
    int K, int lda, int ldb, int ldc,
    const float* __restrict__ bias, const float* __restrict__ resid)
{
    const int AW = 36, BW = 136;                   // smem row strides (words)
    const int AWORDS = 128 * AW, BWORDS = 32 * BW; // 4608 + 4352
    const int STW = AWORDS + BWORDS;               // 8960 words per stage

    extern __shared__ float sm[];

    int t = threadIdx.x, lane = t & 31, warp = t >> 5;
    int g = lane >> 2, tg = lane & 3;
    int wm = (warp >> 2) * 64, wn = (warp & 3) * 32;
    int m0 = blockIdx.y * 128, n0 = blockIdx.x * 128;

    // ldsm lane mapping: matrices {rows,rows+8} x {cols,cols+4}
    int lrow = ((lane >> 3) & 1) * 8 + (lane & 7);   // row within 16-row tile
    int lcol = (lane >> 4) * 4;                      // word col offset (0 or 4)
    uint32_t a_lane_off = (uint32_t)((lrow * AW + lcol) * 4);
    uint32_t sm_u32 = (uint32_t)__cvta_generic_to_shared(sm);

    const float* Ab = A + (size_t)m0 * lda;
    const float* Bb_ = Bm + n0;

    float acc[4][4][4];
    #pragma unroll
    for (int i = 0; i < 4; i++)
        #pragma unroll
        for (int j = 0; j < 4; j++)
            #pragma unroll
            for (int l = 0; l < 4; l++) acc[i][j][l] = 0.f;

    auto issue = [&](int kt, int st) {
        float* As = sm + st * STW;
        float* Bs = As + AWORDS;
        const float* Ag = Ab + kt * 32;
        const float* Bg = Bb_ + (size_t)(kt * 32) * ldb;
        #pragma unroll
        for (int it = 0; it < 4; it++) {           // A: 128x32 = 1024 float4
            int c = t + it * 256;
            int r = c >> 3, c4 = (c & 7) * 4;
            cp16((uint32_t)__cvta_generic_to_shared(As + r * AW + c4),
                 Ag + (size_t)r * lda + c4);
        }
        #pragma unroll
        for (int it = 0; it < 4; it++) {           // B: 32x128 = 1024 float4
            int c = t + it * 256;
            int k = c >> 5, n4 = (c & 31) * 4;
            cp16((uint32_t)__cvta_generic_to_shared(Bs + k * BW + n4),
                 Bg + (size_t)k * ldb + n4);
        }
        CP_COMMIT();
    };

    auto compute = [&](int st) {
        uint32_t As_u32 = sm_u32 + (uint32_t)(st * STW * 4);
        const uint32_t* Bs = reinterpret_cast<const uint32_t*>(sm + st * STW) + AWORDS;
        uint32_t a_base = As_u32 + (uint32_t)(wm * AW * 4) + a_lane_off;
        #pragma unroll
        for (int ks = 0; ks < 4; ks++) {
            int k0 = ks * 8;
            uint32_t af[4][4], bf[4][2];
            #pragma unroll
            for (int mt = 0; mt < 4; mt++)
                ldsm_x4(af[mt], a_base + (uint32_t)((mt * 16 * AW + k0) * 4));
            #pragma unroll
            for (int nt = 0; nt < 4; nt++) {
                int c = wn + nt * 8 + g;
                bf[nt][0] = Bs[(k0 + tg) * BW + c];
                bf[nt][1] = Bs[(k0 + tg + 4) * BW + c];
            }
            #pragma unroll
            for (int mt = 0; mt < 4; mt++)
                #pragma unroll
                for (int nt = 0; nt < 4; nt++)
                    mma_tf32(acc[mt][nt], af[mt], bf[nt]);
        }
    };

    const int KT = K / 32;
    issue(0, 0);
    issue(1, 1);

    for (int kt = 0; kt < KT; kt++) {
        if (kt + 1 < KT) { CP_WAIT(1); } else { CP_WAIT(0); }
        __syncthreads();
        compute(kt % 3);
        if (kt + 2 < KT) issue(kt + 2, (kt + 2) % 3);
    }

    // ---- epilogue ----
    #pragma unroll
    for (int mt = 0; mt < 4; mt++) {
        int r0 = m0 + wm + mt * 16 + g;
        #pragma unroll
        for (int nt = 0; nt < 4; nt++) {
            int c = n0 + wn + nt * 8 + 2 * tg;
            #pragma unroll
            for (int half = 0; half < 2; half++) {
                int r = r0 + half * 8;
                float v0 = acc[mt][nt][half * 2 + 0];
                float v1 = acc[mt][nt][half * 2 + 1];
                if (HAS_BIAS) { v0 += bias[c]; v1 += bias[c + 1]; }
                if (GELU_ACT) {
                    v0 = 0.5f * v0 * (1.0f + erff(v0 * 0.70710678118654752f));
                    v1 = 0.5f * v1 * (1.0f + erff(v1 * 0.70710678118654752f));
                }
                if (HAS_RES) {
                    float2 rv = *reinterpret_cast<const float2*>(
                        resid + (size_t)r * ldc + c);
                    v0 += rv.x; v1 += rv.y;
                }
                if (ROUND_OUT) { v0 = rnd32(v0); v1 = rnd32(v1); }
                float2 ov; ov.x = v0; ov.y = v1;
                *reinterpret_cast<float2*>(Cm + (size_t)r * ldc + c) = ov;
            }
        }
    }
}

// ---------------- fused flash attention (tf32 mma.sync) ----------------
__global__ void __launch_bounds__(256) flash_kernel(
    const float* __restrict__ qkv, const float* __restrict__ kf,
    const float* __restrict__ vf, float* __restrict__ o)
{
    extern __shared__ float fsm[];
    const int TW = 68;
    const int KWORDS = 64 * TW;

    int t = threadIdx.x, lane = t & 31, w = t >> 5;
    int g = lane >> 2, tg = lane & 3;
    int bh = blockIdx.y, b = bh >> 4, h = bh & 15;
    int q0 = blockIdx.x * 128;

    const float* Qg = qkv + ((size_t)(b * NPp + q0)) * C3 + h * HDd;
    #pragma unroll
    for (int it = 0; it < 8; it++) {
        int id = t + it * 256;
        int r = id >> 4, c4 = (id & 15) * 4;
        float4 v = *reinterpret_cast<const float4*>(Qg + (size_t)r * C3 + c4);
        float* d = fsm + r * TW + c4;
        d[0] = v.x; d[1] = v.y; d[2] = v.z; d[3] = v.w;
    }
    __syncthreads();

    uint32_t qf[8][4];
    {
        int r0 = w * 16 + g;
        #pragma unroll
        for (int kk = 0; kk < 8; kk++) {
            qf[kk][0] = f2tf32(fsm[r0 * TW + kk * 8 + tg] * 0.125f);
            qf[kk][1] = f2tf32(fsm[(r0 + 8) * TW + kk * 8 + tg] * 0.125f);
            qf[kk][2] = f2tf32(fsm[r0 * TW + kk * 8 + tg + 4] * 0.125f);
            qf[kk][3] = f2tf32(fsm[(r0 + 8) * TW + kk * 8 + tg + 4] * 0.125f);
        }
    }
    __syncthreads();

    const float* Kg = kf + (size_t)bh * Nn * HDd;
    const float* Vg = vf + (size_t)bh * Nn * HDd;

    auto issue_tile = [&](int j, int buf) {
        float* Ks = fsm + buf * (2 * KWORDS);
        float* Vs = Ks + KWORDS;
        const float* kg = Kg + (size_t)j * 64 * HDd;
        const float* vg = Vg + (size_t)j * 64 * HDd;
        #pragma unroll
        for (int it = 0; it < 4; it++) {
            int id = t + it * 256;
            int r = id >> 4, c4 = (id & 15) * 4;
            cp16((uint32_t)__cvta_generic_to_shared(Ks + r * TW + c4), kg + r * HDd + c4);
            cp16((uint32_t)__cvta_generic_to_shared(Vs + r * TW + c4), vg + r * HDd + c4);
        }
    };

    float m_r[2] = {-1e30f, -1e30f};
    float l_r[2] = {0.f, 0.f};
    float o_acc[8][4];
    #pragma unroll
    for (int i = 0; i < 8; i++)
        #pragma unroll
        for (int j = 0; j < 4; j++) o_acc[i][j] = 0.f;

    const unsigned FULL = 0xffffffffu;
    const int srcA = (lane & ~3) | (tg >> 1);
    const int srcB = srcA + 2;

    issue_tile(0, 0);
    CP_COMMIT();

    for (int j = 0; j < Nn / 64; j++) {
        int buf = j & 1;
        if (j + 1 < Nn / 64) { issue_tile(j + 1, buf ^ 1); CP_COMMIT(); CP_WAIT(1); }
        else                 { CP_WAIT(0); }
        __syncthreads();

        const uint32_t* Ku = reinterpret_cast<const uint32_t*>(fsm + buf * (2 * KWORDS));
        const uint32_t* Vu = Ku + KWORDS;

        float s[8][4];
        #pragma unroll
        for (int nt = 0; nt < 8; nt++)
            #pragma unroll
            for (int i = 0; i < 4; i++) s[nt][i] = 0.f;
        #pragma unroll
        for (int kk = 0; kk < 8; kk++) {
            #pragma unroll
            for (int nt = 0; nt < 8; nt++) {
                uint32_t bb[2];
                bb[0] = Ku[(nt * 8 + g) * TW + kk * 8 + tg];
                bb[1] = Ku[(nt * 8 + g) * TW + kk * 8 + tg + 4];
                mma_tf32(s[nt], qf[kk], bb);
            }
        }

        float mn0 = m_r[0], mn1 = m_r[1];
        #pragma unroll
        for (int nt = 0; nt < 8; nt++) {
            mn0 = fmaxf(mn0, fmaxf(s[nt][0], s[nt][1]));
            mn1 = fmaxf(mn1, fmaxf(s[nt][2], s[nt][3]));
        }
        mn0 = fmaxf(mn0, __shfl_xor_sync(FULL, mn0, 1));
        mn0 = fmaxf(mn0, __shfl_xor_sync(FULL, mn0, 2));
        mn1 = fmaxf(mn1, __shfl_xor_sync(FULL, mn1, 1));
        mn1 = fmaxf(mn1, __shfl_xor_sync(FULL, mn1, 2));
        float c0 = __expf(m_r[0] - mn0);
        float c1 = __expf(m_r[1] - mn1);
        m_r[0] = mn0; m_r[1] = mn1;

        float pf_[8][4];
        float rs0 = 0.f, rs1 = 0.f;
        #pragma unroll
        for (int nt = 0; nt < 8; nt++) {
            pf_[nt][0] = __expf(s[nt][0] - mn0);
            pf_[nt][1] = __expf(s[nt][1] - mn0);
            pf_[nt][2] = __expf(s[nt][2] - mn1);
            pf_[nt][3] = __expf(s[nt][3] - mn1);
            rs0 += pf_[nt][0] + pf_[nt][1];
            rs1 += pf_[nt][2] + pf_[nt][3];
        }
        rs0 += __shfl_xor_sync(FULL, rs0, 1); rs0 += __shfl_xor_sync(FULL, rs0, 2);
        rs1 += __shfl_xor_sync(FULL, rs1, 1); rs1 += __shfl_xor_sync(FULL, rs1, 2);
        l_r[0] = l_r[0] * c0 + rs0;
        l_r[1] = l_r[1] * c1 + rs1;
        #pragma unroll
        for (int nt = 0; nt < 8; nt++) {
            o_acc[nt][0] *= c0; o_acc[nt][1] *= c0;
            o_acc[nt][2] *= c1; o_acc[nt][3] *= c1;
        }

        #pragma unroll
        for (int kk2 = 0; kk2 < 8; kk2++) {
            float v0 = pf_[kk2][0], v1 = pf_[kk2][1], v2 = pf_[kk2][2], v3 = pf_[kk2][3];
            float w0 = __shfl_sync(FULL, v0, srcA), w1 = __shfl_sync(FULL, v1, srcA);
            float w2 = __shfl_sync(FULL, v2, srcA), w3 = __shfl_sync(FULL, v3, srcA);
            float y0 = __shfl_sync(FULL, v0, srcB), y1 = __shfl_sync(FULL, v1, srcB);
            float y2 = __shfl_sync(FULL, v2, srcB), y3 = __shfl_sync(FULL, v3, srcB);
            bool odd = (tg & 1);
            uint32_t af[4];
            af[0] = f2tf32(odd ? w1 : w0);
            af[1] = f2tf32(odd ? w3 : w2);
            af[2] = f2tf32(odd ? y1 : y0);
            af[3] = f2tf32(odd ? y3 : y2);
            #pragma unroll
            for (int nt2 = 0; nt2 < 8; nt2++) {
                uint32_t bb[2];
                bb[0] = Vu[(kk2 * 8 + tg) * TW + nt2 * 8 + g];
                bb[1] = Vu[(kk2 * 8 + tg + 4) * TW + nt2 * 8 + g];
                mma_tf32(o_acc[nt2], af, bb);
            }
        }
        __syncthreads();
    }

    float inv0 = 1.0f / l_r[0], inv1 = 1.0f / l_r[1];
    float* Og = o + ((size_t)(b * NPp + q0 + w * 16 + g)) * Cc + h * HDd;
    #pragma unroll
    for (int nt2 = 0; nt2 < 8; nt2++) {
        int c = nt2 * 8 + 2 * tg;
        float2 r0v; r0v.x = rnd32(o_acc[nt2][0] * inv0); r0v.y = rnd32(o_acc[nt2][1] * inv0);
        float2 r1v; r1v.x = rnd32(o_acc[nt2][2] * inv1); r1v.y = rnd32(o_acc[nt2][3] * inv1);
        *reinterpret_cast<float2*>(Og + c) = r0v;
        *reinterpret_cast<float2*>(Og + (size_t)8 * Cc + c) = r1v;
    }
}

// ---------------- LayerNorm (tf32-rounded output) ----------------
__global__ void ln_kernel(const float* __restrict__ x, const float* __restrict__ g,
                          const float* __restrict__ b, float* __restrict__ out)
{
    size_t row = blockIdx.x;
    const float* xr = x + row * Cc;
    float* orow = out + row * Cc;
    int t = threadIdx.x;
    float4 v = reinterpret_cast<const float4*>(xr)[t];
    float s  = v.x + v.y + v.z + v.w;
    float ss = v.x*v.x + v.y*v.y + v.z*v.z + v.w*v.w;
    #pragma unroll
    for (int o = 16; o > 0; o >>= 1) {
        s  += __shfl_xor_sync(0xffffffffu, s,  o);
        ss += __shfl_xor_sync(0xffffffffu, ss, o);
    }
    __shared__ float r0[8], r1[8];
    if ((t & 31) == 0) { r0[t >> 5] = s; r1[t >> 5] = ss; }
    __syncthreads();
    s = 0.f; ss = 0.f;
    #pragma unroll
    for (int i = 0; i < 8; i++) { s += r0[i]; ss += r1[i]; }
    float mu  = s * (1.0f / Cc);
    float var = ss * (1.0f / Cc) - mu * mu;
    float inv = rsqrtf(var + 1e-5f);
    float4 gv = reinterpret_cast<const float4*>(g)[t];
    float4 bv = reinterpret_cast<const float4*>(b)[t];
    float4 r;
    r.x = rnd32((v.x - mu) * inv * gv.x + bv.x);
    r.y = rnd32((v.y - mu) * inv * gv.y + bv.y);
    r.z = rnd32((v.z - mu) * inv * gv.z + bv.z);
    r.w = rnd32((v.w - mu) * inv * gv.w + bv.w);
    reinterpret_cast<float4*>(orow)[t] = r;
}

// ---------------- mask scan: warp-parallel prefix scan ----------------
__global__ void p2t_kernel(const unsigned* __restrict__ mask)
{
    int b = blockIdx.x;
    int lane = threadIdx.x;
    const unsigned* mrow = mask + b * Nn;
    int base = lane * 32;
    unsigned bits = 0;
    int cnt = 0;
    #pragma unroll
    for (int i = 0; i < 32; i++) {
        unsigned mv = mrow[base + i] != 0u;
        bits |= mv << i;
        cnt += (int)mv;
    }
    int excl = cnt;
    #pragma unroll
    for (int o = 1; o < 32; o <<= 1) {
        int v = __shfl_up_sync(0xffffffffu, excl, o);
        if (lane >= o) excl += v;
    }
    excl -= cnt;
    int run = excl;
    #pragma unroll
    for (int i = 0; i < 32; i++) {
        bool mv = (bits >> i) & 1u;
        g_p2t[b * Nn + base + i] = mv ? run : -1;
        run += mv ? 1 : 0;
    }
}

// ---------------- KV fill (float4), pre-rounds to tf32 ----------------
__global__ void kvfill_kernel(const float4* __restrict__ ck, const float4* __restrict__ cv)
{
    size_t idx = (size_t)blockIdx.x * blockDim.x + threadIdx.x;
    int d4 = idx & 15;
    int n  = (idx >> 4) & (Nn - 1);
    int h  = (idx >> 14) & (Hh - 1);
    int b  = (int)(idx >> 18);
    int tok = g_p2t[b * Nn + n];
    float4 kv, vv;
    if (tok >= 0) {
        const float4* qkv4 = reinterpret_cast<const float4*>(g_qkv);
        size_t q = ((size_t)(b * NPp + tok)) * (C3 / 4) + (Cc / 4) + h * (HDd / 4) + d4;
        kv = qkv4[q];
        vv = qkv4[q + Cc / 4];
    } else {
        kv = ck[idx];
        vv = cv[idx];
    }
    kv.x = rnd32(kv.x); kv.y = rnd32(kv.y); kv.z = rnd32(kv.z); kv.w = rnd32(kv.w);
    vv.x = rnd32(vv.x); vv.y = rnd32(vv.y); vv.z = rnd32(vv.z); vv.w = rnd32(vv.w);
    reinterpret_cast<float4*>(g_kf)[idx] = kv;
    reinterpret_cast<float4*>(g_vf)[idx] = vv;
}

// ---------------- launch ----------------
extern "C" void kernel_launch(void* const* d_in, const int* in_sizes, int n_in,
                              void* d_out, int out_size)
{
    const float*    x      = (const float*)   d_in[0];
    const float*    cachek = (const float*)   d_in[1];
    const float*    cachev = (const float*)   d_in[2];
    const unsigned* mask   = (const unsigned*)d_in[3];
    const float*    qkv_w  = (const float*)   d_in[4];
    const float*    qkv_b  = (const float*)   d_in[5];
    const float*    proj_w = (const float*)   d_in[6];
    const float*    proj_b = (const float*)   d_in[7];
    const float*    n1_g   = (const float*)   d_in[8];
    const float*    n1_b   = (const float*)   d_in[9];
    const float*    n2_g   = (const float*)   d_in[10];
    const float*    n2_b   = (const float*)   d_in[11];
    const float*    fc1_w  = (const float*)   d_in[12];
    const float*    fc1_b  = (const float*)   d_in[13];
    const float*    fc2_w  = (const float*)   d_in[14];
    const float*    fc2_b  = (const float*)   d_in[15];
    float* out = (float*)d_out;

    float *h, *qkv, *kf, *vf, *o, *x1, *hid, *wq, *wp, *w1, *w2;
    cudaGetSymbolAddress((void**)&h,   g_h);
    cudaGetSymbolAddress((void**)&qkv, g_qkv);
    cudaGetSymbolAddress((void**)&kf,  g_kf);
    cudaGetSymbolAddress((void**)&vf,  g_vf);
    cudaGetSymbolAddress((void**)&o,   g_o);
    cudaGetSymbolAddress((void**)&x1,  g_x1);
    cudaGetSymbolAddress((void**)&hid, g_hid);
    cudaGetSymbolAddress((void**)&wq,  g_wq);
    cudaGetSymbolAddress((void**)&wp,  g_wp);
    cudaGetSymbolAddress((void**)&w1,  g_w1);
    cudaGetSymbolAddress((void**)&w2,  g_w2);

    const int GEMM_SMEM  = 3 * (128 * 36 + 32 * 136) * 4;   // 107520 B
    const int FLASH_SMEM = 2 * 2 * 64 * 68 * 4;             // 69632 B
    cudaFuncSetAttribute((const void*)mma_gemm<true, false, false, true>,
                         cudaFuncAttributeMaxDynamicSharedMemorySize, GEMM_SMEM);
    cudaFuncSetAttribute((const void*)mma_gemm<true, false, true, false>,
                         cudaFuncAttributeMaxDynamicSharedMemorySize, GEMM_SMEM);
    cudaFuncSetAttribute((const void*)mma_gemm<true, true, false, true>,
                         cudaFuncAttributeMaxDynamicSharedMemorySize, GEMM_SMEM);
    cudaFuncSetAttribute(flash_kernel,
                         cudaFuncAttributeMaxDynamicSharedMemorySize, FLASH_SMEM);

    // 0. pre-round all weights to tf32 (one launch)
    round_all_kernel<<<3145728 / 256, 256>>>(
        (const float4*)qkv_w, (const float4*)proj_w,
        (const float4*)fc1_w, (const float4*)fc2_w);

    // 1. LN1 (rounded out)
    ln_kernel<<<Mtok, 256>>>(x, n1_g, n1_b, h);

    // 2. QKV = h @ wq + qkv_b  (rounded out)
    mma_gemm<true, false, false, true><<<dim3(C3 / 128, Mtok / 128), 256, GEMM_SMEM>>>(
        h, wq, qkv, Cc, Cc, C3, C3, qkv_b, nullptr);

    // 3. mask scan (warp-parallel)
    p2t_kernel<<<Bb, 32>>>(mask);

    // 4. KV full fill (tf32-rounded)
    kvfill_kernel<<<((Bb * Hh * Nn * HDd) / 4) / 256, 256>>>(
        (const float4*)cachek, (const float4*)cachev);

    // 5-7. fused attention (o rounded out)
    flash_kernel<<<dim3(NPp / 128, Bb * Hh), 256, FLASH_SMEM>>>(qkv, kf, vf, o);

    // 8. x1 = x + o @ wp + proj_b
    mma_gemm<true, false, true, false><<<dim3(Cc / 128, Mtok / 128), 256, GEMM_SMEM>>>(
        o, wp, x1, Cc, Cc, Cc, Cc, proj_b, x);

    // 9. LN2 (rounded out)
    ln_kernel<<<Mtok, 256>>>(x1, n2_g, n2_b, h);

    // 10. hid = gelu(h @ w1 + fc1_b)  (rounded out)
    mma_gemm<true, true, false, true><<<dim3(HIDh / 128, Mtok / 128), 256, GEMM_SMEM>>>(
        h, w1, hid, Cc, Cc, HIDh, HIDh, fc1_b, nullptr);

    // 11. out = x1 + hid @ w2 + fc2_b
    mma_gemm<true, false, true, false><<<dim3(Cc / 128, Mtok / 128), 256, GEMM_SMEM>>>(
        hid, w2, out, HIDh, HIDh, Cc, Cc, fc2_b, x1);
}

// round 12
// speedup vs baseline: 1.4719x; 1.4719x over previous
#include <cuda_runtime.h>
#include <math.h>
#include <stdint.h>

// Problem constants
#define Bb   16
#define NPp  512
#define Nn   1024
#define Cc   1024
#define Hh   16
#define HDd  64
#define C3   3072
#define HIDh 4096
#define Mtok 8192   // B*NP

// ---------------- scratch (device globals) ----------------
__device__ float g_h   [(size_t)Mtok * Cc];
__device__ float g_qkv [(size_t)Mtok * C3];
__device__ float g_kf  [(size_t)Bb * Hh * Nn * HDd];
__device__ float g_vf  [(size_t)Bb * Hh * Nn * HDd];
__device__ float g_o   [(size_t)Mtok * Cc];
__device__ float g_x1  [(size_t)Mtok * Cc];
__device__ float g_hid [(size_t)Mtok * HIDh];
__device__ int   g_p2t [Bb * Nn];
// tf32-rounded weights
__device__ float g_wq  [(size_t)Cc * C3];
__device__ float g_wp  [(size_t)Cc * Cc];
__device__ float g_w1  [(size_t)Cc * HIDh];
__device__ float g_w2  [(size_t)HIDh * Cc];

// ---------------- helpers ----------------
__device__ __forceinline__ uint32_t f2tf32(float f) {
    uint32_t u;
    asm("cvt.rna.tf32.f32 %0, %1;" : "=r"(u) : "f"(f));
    return u;
}
__device__ __forceinline__ float rnd32(float f) { return __uint_as_float(f2tf32(f)); }

__device__ __forceinline__ void mma_tf32(float c[4], const uint32_t a[4], const uint32_t b[2]) {
    asm volatile(
        "mma.sync.aligned.m16n8k8.row.col.f32.tf32.tf32.f32 "
        "{%0,%1,%2,%3}, {%4,%5,%6,%7}, {%8,%9}, {%0,%1,%2,%3};"
        : "+f"(c[0]), "+f"(c[1]), "+f"(c[2]), "+f"(c[3])
        : "r"(a[0]), "r"(a[1]), "r"(a[2]), "r"(a[3]), "r"(b[0]), "r"(b[1]));
}
__device__ __forceinline__ void cp16(uint32_t saddr, const void* g) {
    asm volatile("cp.async.cg.shared.global [%0], [%1], 16;" :: "r"(saddr), "l"(g));
}
#define CP_COMMIT() asm volatile("cp.async.commit_group;")
#define CP_WAIT(n)  asm volatile("cp.async.wait_group %0;" :: "n"(n))

// ---------------- weight pre-round: all four weights in one launch ----------------
__global__ void round_all_kernel(const float4* __restrict__ wq_in, const float4* __restrict__ wp_in,
                                 const float4* __restrict__ w1_in, const float4* __restrict__ w2_in)
{
    const size_t NQ = (size_t)Cc * C3 / 4;
    const size_t NP_ = (size_t)Cc * Cc / 4;
    const size_t N1 = (size_t)Cc * HIDh / 4;
    const size_t N2 = (size_t)HIDh * Cc / 4;
    size_t i = (size_t)blockIdx.x * blockDim.x + threadIdx.x;
    const float4* src; float4* dst; size_t off;
    if (i < NQ)                    { src = wq_in; dst = (float4*)g_wq; off = i; }
    else if (i < NQ + NP_)         { src = wp_in; dst = (float4*)g_wp; off = i - NQ; }
    else if (i < NQ + NP_ + N1)    { src = w1_in; dst = (float4*)g_w1; off = i - NQ - NP_; }
    else if (i < NQ + NP_ + N1+N2) { src = w2_in; dst = (float4*)g_w2; off = i - NQ - NP_ - N1; }
    else return;
    float4 v = src[off];
    v.x = rnd32(v.x); v.y = rnd32(v.y); v.z = rnd32(v.z); v.w = rnd32(v.w);
    dst[off] = v;
}

// ---------------- tf32 mma.sync GEMM, cp.async 3-stage, BK=32 (R10 exact) ----------------
// C[M,N] = act(A @ B + bias) + resid ;  A:[M,K] row-major, B:[K,N] row-major.
// BM=128, BN=128, BK=32; 256 thr = 8 warps, warp tile 64x32. 2 blocks/SM (16 warps).
template<bool HAS_BIAS, bool GELU_ACT, bool HAS_RES, bool ROUND_OUT>
__global__ void __launch_bounds__(256) mma_gemm(
    const float* __restrict__ A, const float* __restrict__ Bm, float* __restrict__ Cm,
    int K, int lda, int ldb, int ldc,
    const float* __restrict__ bias, const float* __restrict__ resid)
{
    const int AW = 36, BW = 136;                   // smem row strides (words)
    const int AWORDS = 128 * AW, BWORDS = 32 * BW; // 4608 + 4352
    const int STW = AWORDS + BWORDS;               // 8960 words per stage

    extern __shared__ float sm[];

    int t = threadIdx.x, lane = t & 31, warp = t >> 5;
    int g = lane >> 2, tg = lane & 3;
    int wm = (warp >> 2) * 64, wn = (warp & 3) * 32;
    int m0 = blockIdx.y * 128, n0 = blockIdx.x * 128;

    const float* Ab = A + (size_t)m0 * lda;
    const float* Bb_ = Bm + n0;

    float acc[4][4][4];
    #pragma unroll
    for (int i = 0; i < 4; i++)
        #pragma unroll
        for (int j = 0; j < 4; j++)
            #pragma unroll
            for (int l = 0; l < 4; l++) acc[i][j][l] = 0.f;

    auto issue = [&](int kt, int st) {
        float* As = sm + st * STW;
        float* Bs = As + AWORDS;
        const float* Ag = Ab + kt * 32;
        const float* Bg = Bb_ + (size_t)(kt * 32) * ldb;
        #pragma unroll
        for (int it = 0; it < 4; it++) {           // A: 128x32 = 1024 float4
            int c = t + it * 256;
            int r = c >> 3, c4 = (c & 7) * 4;
            cp16((uint32_t)__cvta_generic_to_shared(As + r * AW + c4),
                 Ag + (size_t)r * lda + c4);
        }
        #pragma unroll
        for (int it = 0; it < 4; it++) {           // B: 32x128 = 1024 float4
            int c = t + it * 256;
            int k = c >> 5, n4 = (c & 31) * 4;
            cp16((uint32_t)__cvta_generic_to_shared(Bs + k * BW + n4),
                 Bg + (size_t)k * ldb + n4);
        }
        CP_COMMIT();
    };

    auto compute = [&](int st) {
        const uint32_t* As = reinterpret_cast<const uint32_t*>(sm + st * STW);
        const uint32_t* Bs = As + AWORDS;
        #pragma unroll
        for (int ks = 0; ks < 4; ks++) {
            int k0 = ks * 8;
            uint32_t af[4][4], bf[4][2];
            #pragma unroll
            for (int mt = 0; mt < 4; mt++) {
                int r = wm + mt * 16 + g;
                af[mt][0] = As[r * AW + k0 + tg];
                af[mt][1] = As[(r + 8) * AW + k0 + tg];
                af[mt][2] = As[r * AW + k0 + tg + 4];
                af[mt][3] = As[(r + 8) * AW + k0 + tg + 4];
            }
            #pragma unroll
            for (int nt = 0; nt < 4; nt++) {
                int c = wn + nt * 8 + g;
                bf[nt][0] = Bs[(k0 + tg) * BW + c];
                bf[nt][1] = Bs[(k0 + tg + 4) * BW + c];
            }
            #pragma unroll
            for (int mt = 0; mt < 4; mt++)
                #pragma unroll
                for (int nt = 0; nt < 4; nt++)
                    mma_tf32(acc[mt][nt], af[mt], bf[nt]);
        }
    };

    const int KT = K / 32;
    issue(0, 0);
    issue(1, 1);

    for (int kt = 0; kt < KT; kt++) {
        if (kt + 1 < KT) { CP_WAIT(1); } else { CP_WAIT(0); }
        __syncthreads();
        compute(kt % 3);
        if (kt + 2 < KT) issue(kt + 2, (kt + 2) % 3);
    }

    // ---- epilogue ----
    #pragma unroll
    for (int mt = 0; mt < 4; mt++) {
        int r0 = m0 + wm + mt * 16 + g;
        #pragma unroll
        for (int nt = 0; nt < 4; nt++) {
            int c = n0 + wn + nt * 8 + 2 * tg;
            #pragma unroll
            for (int half = 0; half < 2; half++) {
                int r = r0 + half * 8;
                float v0 = acc[mt][nt][half * 2 + 0];
                float v1 = acc[mt][nt][half * 2 + 1];
                if (HAS_BIAS) { v0 += bias[c]; v1 += bias[c + 1]; }
                if (GELU_ACT) {
                    v0 = 0.5f * v0 * (1.0f + erff(v0 * 0.70710678118654752f));
                    v1 = 0.5f * v1 * (1.0f + erff(v1 * 0.70710678118654752f));
                }
                if (HAS_RES) {
                    float2 rv = *reinterpret_cast<const float2*>(
                        resid + (size_t)r * ldc + c);
                    v0 += rv.x; v1 += rv.y;
                }
                if (ROUND_OUT) { v0 = rnd32(v0); v1 = rnd32(v1); }
                float2 ov; ov.x = v0; ov.y = v1;
                *reinterpret_cast<float2*>(Cm + (size_t)r * ldc + c) = ov;
            }
        }
    }
}

// ---------------- fused flash attention (tf32 mma.sync) ----------------
__global__ void __launch_bounds__(256) flash_kernel(
    const float* __restrict__ qkv, const float* __restrict__ kf,
    const float* __restrict__ vf, float* __restrict__ o)
{
    extern __shared__ float fsm[];
    const int TW = 68;
    const int KWORDS = 64 * TW;

    int t = threadIdx.x, lane = t & 31, w = t >> 5;
    int g = lane >> 2, tg = lane & 3;
    int bh = blockIdx.y, b = bh >> 4, h = bh & 15;
    int q0 = blockIdx.x * 128;

    const float* Qg = qkv + ((size_t)(b * NPp + q0)) * C3 + h * HDd;
    #pragma unroll
    for (int it = 0; it < 8; it++) {
        int id = t + it * 256;
        int r = id >> 4, c4 = (id & 15) * 4;
        float4 v = *reinterpret_cast<const float4*>(Qg + (size_t)r * C3 + c4);
        float* d = fsm + r * TW + c4;
        d[0] = v.x; d[1] = v.y; d[2] = v.z; d[3] = v.w;
    }
    __syncthreads();

    uint32_t qf[8][4];
    {
        int r0 = w * 16 + g;
        #pragma unroll
        for (int kk = 0; kk < 8; kk++) {
            qf[kk][0] = f2tf32(fsm[r0 * TW + kk * 8 + tg] * 0.125f);
            qf[kk][1] = f2tf32(fsm[(r0 + 8) * TW + kk * 8 + tg] * 0.125f);
            qf[kk][2] = f2tf32(fsm[r0 * TW + kk * 8 + tg + 4] * 0.125f);
            qf[kk][3] = f2tf32(fsm[(r0 + 8) * TW + kk * 8 + tg + 4] * 0.125f);
        }
    }
    __syncthreads();

    const float* Kg = kf + (size_t)bh * Nn * HDd;
    const float* Vg = vf + (size_t)bh * Nn * HDd;

    auto issue_tile = [&](int j, int buf) {
        float* Ks = fsm + buf * (2 * KWORDS);
        float* Vs = Ks + KWORDS;
        const float* kg = Kg + (size_t)j * 64 * HDd;
        const float* vg = Vg + (size_t)j * 64 * HDd;
        #pragma unroll
        for (int it = 0; it < 4; it++) {
            int id = t + it * 256;
            int r = id >> 4, c4 = (id & 15) * 4;
            cp16((uint32_t)__cvta_generic_to_shared(Ks + r * TW + c4), kg + r * HDd + c4);
            cp16((uint32_t)__cvta_generic_to_shared(Vs + r * TW + c4), vg + r * HDd + c4);
        }
    };

    float m_r[2] = {-1e30f, -1e30f};
    float l_r[2] = {0.f, 0.f};
    float o_acc[8][4];
    #pragma unroll
    for (int i = 0; i < 8; i++)
        #pragma unroll
        for (int j = 0; j < 4; j++) o_acc[i][j] = 0.f;

    const unsigned FULL = 0xffffffffu;
    const int srcA = (lane & ~3) | (tg >> 1);
    const int srcB = srcA + 2;

    issue_tile(0, 0);
    CP_COMMIT();

    for (int j = 0; j < Nn / 64; j++) {
        int buf = j & 1;
        if (j + 1 < Nn / 64) { issue_tile(j + 1, buf ^ 1); CP_COMMIT(); CP_WAIT(1); }
        else                 { CP_WAIT(0); }
        __syncthreads();

        const uint32_t* Ku = reinterpret_cast<const uint32_t*>(fsm + buf * (2 * KWORDS));
        const uint32_t* Vu = Ku + KWORDS;

        float s[8][4];
        #pragma unroll
        for (int nt = 0; nt < 8; nt++)
            #pragma unroll
            for (int i = 0; i < 4; i++) s[nt][i] = 0.f;
        #pragma unroll
        for (int kk = 0; kk < 8; kk++) {
            #pragma unroll
            for (int nt = 0; nt < 8; nt++) {
                uint32_t bb[2];
                bb[0] = Ku[(nt * 8 + g) * TW + kk * 8 + tg];
                bb[1] = Ku[(nt * 8 + g) * TW + kk * 8 + tg + 4];
                mma_tf32(s[nt], qf[kk], bb);
            }
        }

        float mn0 = m_r[0], mn1 = m_r[1];
        #pragma unroll
        for (int nt = 0; nt < 8; nt++) {
            mn0 = fmaxf(mn0, fmaxf(s[nt][0], s[nt][1]));
            mn1 = fmaxf(mn1, fmaxf(s[nt][2], s[nt][3]));
        }
        mn0 = fmaxf(mn0, __shfl_xor_sync(FULL, mn0, 1));
        mn0 = fmaxf(mn0, __shfl_xor_sync(FULL, mn0, 2));
        mn1 = fmaxf(mn1, __shfl_xor_sync(FULL, mn1, 1));
        mn1 = fmaxf(mn1, __shfl_xor_sync(FULL, mn1, 2));
        float c0 = __expf(m_r[0] - mn0);
        float c1 = __expf(m_r[1] - mn1);
        m_r[0] = mn0; m_r[1] = mn1;

        float pf_[8][4];
        float rs0 = 0.f, rs1 = 0.f;
        #pragma unroll
        for (int nt = 0; nt < 8; nt++) {
            pf_[nt][0] = __expf(s[nt][0] - mn0);
            pf_[nt][1] = __expf(s[nt][1] - mn0);
            pf_[nt][2] = __expf(s[nt][2] - mn1);
            pf_[nt][3] = __expf(s[nt][3] - mn1);
            rs0 += pf_[nt][0] + pf_[nt][1];
            rs1 += pf_[nt][2] + pf_[nt][3];
        }
        rs0 += __shfl_xor_sync(FULL, rs0, 1); rs0 += __shfl_xor_sync(FULL, rs0, 2);
        rs1 += __shfl_xor_sync(FULL, rs1, 1); rs1 += __shfl_xor_sync(FULL, rs1, 2);
        l_r[0] = l_r[0] * c0 + rs0;
        l_r[1] = l_r[1] * c1 + rs1;
        #pragma unroll
        for (int nt = 0; nt < 8; nt++) {
            o_acc[nt][0] *= c0; o_acc[nt][1] *= c0;
            o_acc[nt][2] *= c1; o_acc[nt][3] *= c1;
        }

        #pragma unroll
        for (int kk2 = 0; kk2 < 8; kk2++) {
            float v0 = pf_[kk2][0], v1 = pf_[kk2][1], v2 = pf_[kk2][2], v3 = pf_[kk2][3];
            float w0 = __shfl_sync(FULL, v0, srcA), w1 = __shfl_sync(FULL, v1, srcA);
            float w2 = __shfl_sync(FULL, v2, srcA), w3 = __shfl_sync(FULL, v3, srcA);
            float y0 = __shfl_sync(FULL, v0, srcB), y1 = __shfl_sync(FULL, v1, srcB);
            float y2 = __shfl_sync(FULL, v2, srcB), y3 = __shfl_sync(FULL, v3, srcB);
            bool odd = (tg & 1);
            uint32_t af[4];
            af[0] = f2tf32(odd ? w1 : w0);
            af[1] = f2tf32(odd ? w3 : w2);
            af[2] = f2tf32(odd ? y1 : y0);
            af[3] = f2tf32(odd ? y3 : y2);
            #pragma unroll
            for (int nt2 = 0; nt2 < 8; nt2++) {
                uint32_t bb[2];
                bb[0] = Vu[(kk2 * 8 + tg) * TW + nt2 * 8 + g];
                bb[1] = Vu[(kk2 * 8 + tg + 4) * TW + nt2 * 8 + g];
                mma_tf32(o_acc[nt2], af, bb);
            }
        }
        __syncthreads();
    }

    float inv0 = 1.0f / l_r[0], inv1 = 1.0f / l_r[1];
    float* Og = o + ((size_t)(b * NPp + q0 + w * 16 + g)) * Cc + h * HDd;
    #pragma unroll
    for (int nt2 = 0; nt2 < 8; nt2++) {
        int c = nt2 * 8 + 2 * tg;
        float2 r0v; r0v.x = rnd32(o_acc[nt2][0] * inv0); r0v.y = rnd32(o_acc[nt2][1] * inv0);
        float2 r1v; r1v.x = rnd32(o_acc[nt2][2] * inv1); r1v.y = rnd32(o_acc[nt2][3] * inv1);
        *reinterpret_cast<float2*>(Og + c) = r0v;
        *reinterpret_cast<float2*>(Og + (size_t)8 * Cc + c) = r1v;
    }
}

// ---------------- LayerNorm (tf32-rounded output) ----------------
__global__ void ln_kernel(const float* __restrict__ x, const float* __restrict__ g,
                          const float* __restrict__ b, float* __restrict__ out)
{
    size_t row = blockIdx.x;
    const float* xr = x + row * Cc;
    float* orow = out + row * Cc;
    int t = threadIdx.x;
    float4 v = reinterpret_cast<const float4*>(xr)[t];
    float s  = v.x + v.y + v.z + v.w;
    float ss = v.x*v.x + v.y*v.y + v.z*v.z + v.w*v.w;
    #pragma unroll
    for (int o = 16; o > 0; o >>= 1) {
        s  += __shfl_xor_sync(0xffffffffu, s,  o);
        ss += __shfl_xor_sync(0xffffffffu, ss, o);
    }
    __shared__ float r0[8], r1[8];
    if ((t & 31) == 0) { r0[t >> 5] = s; r1[t >> 5] = ss; }
    __syncthreads();
    s = 0.f; ss = 0.f;
    #pragma unroll
    for (int i = 0; i < 8; i++) { s += r0[i]; ss += r1[i]; }
    float mu  = s * (1.0f / Cc);
    float var = ss * (1.0f / Cc) - mu * mu;
    float inv = rsqrtf(var + 1e-5f);
    float4 gv = reinterpret_cast<const float4*>(g)[t];
    float4 bv = reinterpret_cast<const float4*>(b)[t];
    float4 r;
    r.x = rnd32((v.x - mu) * inv * gv.x + bv.x);
    r.y = rnd32((v.y - mu) * inv * gv.y + bv.y);
    r.z = rnd32((v.z - mu) * inv * gv.z + bv.z);
    r.w = rnd32((v.w - mu) * inv * gv.w + bv.w);
    reinterpret_cast<float4*>(orow)[t] = r;
}

// ---------------- mask scan: warp-parallel prefix scan ----------------
__global__ void p2t_kernel(const unsigned* __restrict__ mask)
{
    int b = blockIdx.x;
    int lane = threadIdx.x;
    const unsigned* mrow = mask + b * Nn;
    int base = lane * 32;
    unsigned bits = 0;
    int cnt = 0;
    #pragma unroll
    for (int i = 0; i < 32; i++) {
        unsigned mv = mrow[base + i] != 0u;
        bits |= mv << i;
        cnt += (int)mv;
    }
    int excl = cnt;
    #pragma unroll
    for (int o = 1; o < 32; o <<= 1) {
        int v = __shfl_up_sync(0xffffffffu, excl, o);
        if (lane >= o) excl += v;
    }
    excl -= cnt;
    int run = excl;
    #pragma unroll
    for (int i = 0; i < 32; i++) {
        bool mv = (bits >> i) & 1u;
        g_p2t[b * Nn + base + i] = mv ? run : -1;
        run += mv ? 1 : 0;
    }
}

// ---------------- KV fill (float4), pre-rounds to tf32 ----------------
__global__ void kvfill_kernel(const float4* __restrict__ ck, const float4* __restrict__ cv)
{
    size_t idx = (size_t)blockIdx.x * blockDim.x + threadIdx.x;
    int d4 = idx & 15;
    int n  = (idx >> 4) & (Nn - 1);
    int h  = (idx >> 14) & (Hh - 1);
    int b  = (int)(idx >> 18);
    int tok = g_p2t[b * Nn + n];
    float4 kv, vv;
    if (tok >= 0) {
        const float4* qkv4 = reinterpret_cast<const float4*>(g_qkv);
        size_t q = ((size_t)(b * NPp + tok)) * (C3 / 4) + (Cc / 4) + h * (HDd / 4) + d4;
        kv = qkv4[q];
        vv = qkv4[q + Cc / 4];
    } else {
        kv = ck[idx];
        vv = cv[idx];
    }
    kv.x = rnd32(kv.x); kv.y = rnd32(kv.y); kv.z = rnd32(kv.z); kv.w = rnd32(kv.w);
    vv.x = rnd32(vv.x); vv.y = rnd32(vv.y); vv.z = rnd32(vv.z); vv.w = rnd32(vv.w);
    reinterpret_cast<float4*>(g_kf)[idx] = kv;
    reinterpret_cast<float4*>(g_vf)[idx] = vv;
}

// ---------------- launch ----------------
extern "C" void kernel_launch(void* const* d_in, const int* in_sizes, int n_in,
                              void* d_out, int out_size)
{
    const float*    x      = (const float*)   d_in[0];
    const float*    cachek = (const float*)   d_in[1];
    const float*    cachev = (const float*)   d_in[2];
    const unsigned* mask   = (const unsigned*)d_in[3];
    const float*    qkv_w  = (const float*)   d_in[4];
    const float*    qkv_b  = (const float*)   d_in[5];
    const float*    proj_w = (const float*)   d_in[6];
    const float*    proj_b = (const float*)   d_in[7];
    const float*    n1_g   = (const float*)   d_in[8];
    const float*    n1_b   = (const float*)   d_in[9];
    const float*    n2_g   = (const float*)   d_in[10];
    const float*    n2_b   = (const float*)   d_in[11];
    const float*    fc1_w  = (const float*)   d_in[12];
    const float*    fc1_b  = (const float*)   d_in[13];
    const float*    fc2_w  = (const float*)   d_in[14];
    const float*    fc2_b  = (const float*)   d_in[15];
    float* out = (float*)d_out;

    float *h, *qkv, *kf, *vf, *o, *x1, *hid, *wq, *wp, *w1, *w2;
    cudaGetSymbolAddress((void**)&h,   g_h);
    cudaGetSymbolAddress((void**)&qkv, g_qkv);
    cudaGetSymbolAddress((void**)&kf,  g_kf);
    cudaGetSymbolAddress((void**)&vf,  g_vf);
    cudaGetSymbolAddress((void**)&o,   g_o);
    cudaGetSymbolAddress((void**)&x1,  g_x1);
    cudaGetSymbolAddress((void**)&hid, g_hid);
    cudaGetSymbolAddress((void**)&wq,  g_wq);
    cudaGetSymbolAddress((void**)&wp,  g_wp);
    cudaGetSymbolAddress((void**)&w1,  g_w1);
    cudaGetSymbolAddress((void**)&w2,  g_w2);

    const int GEMM_SMEM  = 3 * (128 * 36 + 32 * 136) * 4;   // 107520 B
    const int FLASH_SMEM = 2 * 2 * 64 * 68 * 4;             // 69632 B
    cudaFuncSetAttribute((const void*)mma_gemm<true, false, false, true>,
                         cudaFuncAttributeMaxDynamicSharedMemorySize, GEMM_SMEM);
    cudaFuncSetAttribute((const void*)mma_gemm<true, false, true, false>,
                         cudaFuncAttributeMaxDynamicSharedMemorySize, GEMM_SMEM);
    cudaFuncSetAttribute((const void*)mma_gemm<true, true, false, true>,
                         cudaFuncAttributeMaxDynamicSharedMemorySize, GEMM_SMEM);
    cudaFuncSetAttribute(flash_kernel,
                         cudaFuncAttributeMaxDynamicSharedMemorySize, FLASH_SMEM);

    // 0. pre-round all weights to tf32 (one launch)
    round_all_kernel<<<3145728 / 256, 256>>>(
        (const float4*)qkv_w, (const float4*)proj_w,
        (const float4*)fc1_w, (const float4*)fc2_w);

    // 1. LN1 (rounded out)
    ln_kernel<<<Mtok, 256>>>(x, n1_g, n1_b, h);

    // 2. QKV = h @ wq + qkv_b  (rounded out)
    mma_gemm<true, false, false, true><<<dim3(C3 / 128, Mtok / 128), 256, GEMM_SMEM>>>(
        h, wq, qkv, Cc, Cc, C3, C3, qkv_b, nullptr);

    // 3. mask scan (warp-parallel)
    p2t_kernel<<<Bb, 32>>>(mask);

    // 4. KV full fill (tf32-rounded)
    kvfill_kernel<<<((Bb * Hh * Nn * HDd) / 4) / 256, 256>>>(
        (const float4*)cachek, (const float4*)cachev);

    // 5-7. fused attention (o rounded out)
    flash_kernel<<<dim3(NPp / 128, Bb * Hh), 256, FLASH_SMEM>>>(qkv, kf, vf, o);

    // 8. x1 = x + o @ wp + proj_b
    mma_gemm<true, false, true, false><<<dim3(Cc / 128, Mtok / 128), 256, GEMM_SMEM>>>(
        o, wp, x1, Cc, Cc, Cc, Cc, proj_b, x);

    // 9. LN2 (rounded out)
    ln_kernel<<<Mtok, 256>>>(x1, n2_g, n2_b, h);

    // 10. hid = gelu(h @ w1 + fc1_b)  (rounded out)
    mma_gemm<true, true, false, true><<<dim3(HIDh / 128, Mtok / 128), 256, GEMM_SMEM>>>(
        h, w1, hid, Cc, Cc, HIDh, HIDh, fc1_b, nullptr);

    // 11. out = x1 + hid @ w2 + fc2_b
    mma_gemm<true, false, true, false><<<dim3(Cc / 128, Mtok / 128), 256, GEMM_SMEM>>>(
        hid, w2, out, HIDh, HIDh, Cc, Cc, fc2_b, x1);
}

// round 13
// speedup vs baseline: 2.0656x; 1.4033x over previous
#include <cuda_runtime.h>
#include <cuda_fp16.h>
#include <math.h>
#include <stdint.h>

// Problem constants
#define Bb   16
#define NPp  512
#define Nn   1024
#define Cc   1024
#define Hh   16
#define HDd  64
#define C3   3072
#define HIDh 4096
#define Mtok 8192   // B*NP

// ---------------- scratch (device globals) ----------------
__device__ __half g_h  [(size_t)Mtok * Cc];          // LN out (half)
__device__ float  g_qkv[(size_t)Mtok * C3];          // QKV (float)
__device__ float  g_kf [(size_t)Bb * Hh * Nn * HDd]; // K full (tf32-rounded float)
__device__ float  g_vf [(size_t)Bb * Hh * Nn * HDd]; // V full
__device__ __half g_o  [(size_t)Mtok * Cc];          // attention out (half)
__device__ float  g_x1 [(size_t)Mtok * Cc];          // x + proj (float)
__device__ __half g_hid[(size_t)Mtok * HIDh];        // MLP hidden (half)
__device__ int    g_p2t[Bb * Nn];
// half, transposed [N][K] weights
__device__ __half g_wq [(size_t)C3 * Cc];
__device__ __half g_wp [(size_t)Cc * Cc];
__device__ __half g_w1 [(size_t)HIDh * Cc];
__device__ __half g_w2 [(size_t)Cc * HIDh];

// ---------------- helpers ----------------
__device__ __forceinline__ uint32_t f2tf32(float f) {
    uint32_t u;
    asm("cvt.rna.tf32.f32 %0, %1;" : "=r"(u) : "f"(f));
    return u;
}
__device__ __forceinline__ float rnd32(float f) { return __uint_as_float(f2tf32(f)); }

__device__ __forceinline__ void mma_tf32(float c[4], const uint32_t a[4], const uint32_t b[2]) {
    asm volatile(
        "mma.sync.aligned.m16n8k8.row.col.f32.tf32.tf32.f32 "
        "{%0,%1,%2,%3}, {%4,%5,%6,%7}, {%8,%9}, {%0,%1,%2,%3};"
        : "+f"(c[0]), "+f"(c[1]), "+f"(c[2]), "+f"(c[3])
        : "r"(a[0]), "r"(a[1]), "r"(a[2]), "r"(a[3]), "r"(b[0]), "r"(b[1]));
}
__device__ __forceinline__ void mma_f16(float c[4], const uint32_t a[4], const uint32_t b[2]) {
    asm volatile(
        "mma.sync.aligned.m16n8k16.row.col.f32.f16.f16.f32 "
        "{%0,%1,%2,%3}, {%4,%5,%6,%7}, {%8,%9}, {%0,%1,%2,%3};"
        : "+f"(c[0]), "+f"(c[1]), "+f"(c[2]), "+f"(c[3])
        : "r"(a[0]), "r"(a[1]), "r"(a[2]), "r"(a[3]), "r"(b[0]), "r"(b[1]));
}
__device__ __forceinline__ void cp16(uint32_t saddr, const void* g) {
    asm volatile("cp.async.cg.shared.global [%0], [%1], 16;" :: "r"(saddr), "l"(g));
}
#define CP_COMMIT() asm volatile("cp.async.commit_group;")
#define CP_WAIT(n)  asm volatile("cp.async.wait_group %0;" :: "n"(n))

// ---------------- weight pre-round+transpose: float [K][N] -> half [N][K] ----------------
__global__ void wtrans_kernel(const float* __restrict__ wq, const float* __restrict__ wp,
                              const float* __restrict__ w1, const float* __restrict__ w2)
{
    __shared__ __half tile[32][33];
    int bid = blockIdx.x;
    const float* src; __half* dst; int K_, N_, tk, tn;
    if (bid < 3072)      { src = wq; dst = g_wq; K_ = Cc;   N_ = C3;   int id = bid;        tk = id / 96;  tn = id % 96; }
    else if (bid < 4096) { src = wp; dst = g_wp; K_ = Cc;   N_ = Cc;   int id = bid - 3072; tk = id / 32;  tn = id % 32; }
    else if (bid < 8192) { src = w1; dst = g_w1; K_ = Cc;   N_ = HIDh; int id = bid - 4096; tk = id / 128; tn = id % 128; }
    else                 { src = w2; dst = g_w2; K_ = HIDh; N_ = Cc;   int id = bid - 8192; tk = id / 32;  tn = id % 32; }
    int k0 = tk * 32, n0 = tn * 32;
    int t = threadIdx.x;
    #pragma unroll
    for (int it = 0; it < 4; it++) {
        int id = t + it * 256;
        int kk = id >> 5, nn = id & 31;
        tile[kk][nn] = __float2half_rn(src[(size_t)(k0 + kk) * N_ + n0 + nn]);
    }
    __syncthreads();
    #pragma unroll
    for (int it = 0; it < 4; it++) {
        int id = t + it * 256;
        int nn = id >> 5, kk = id & 31;
        dst[(size_t)(n0 + nn) * K_ + k0 + kk] = tile[kk][nn];
    }
}

// ---------------- fp16 mma.sync GEMM, cp.async 3-stage, BK=32 ----------------
// C = act(A @ B^T + bias) + resid ; A: half [M][K] row-major, B: half [N][K] (K-major).
// BM=128, BN=128, BK=32; 256 thr = 8 warps, warp tile 64x32.
template<bool OUT_HALF, bool GELU_ACT, bool HAS_RES>
__global__ void __launch_bounds__(256) mma_gemm(
    const __half* __restrict__ A, const __half* __restrict__ Bm, void* __restrict__ Cm,
    int K, int lda, int ldb, int ldc,
    const float* __restrict__ bias, const float* __restrict__ resid)
{
    const int AW = 20, BW = 20;                    // smem row strides (32-bit words; 40 halves)
    const int AWORDS = 128 * AW, BWORDS = 128 * BW;
    const int STW = AWORDS + BWORDS;               // 5120 words per stage

    extern __shared__ float sm[];

    int t = threadIdx.x, lane = t & 31, warp = t >> 5;
    int g = lane >> 2, tg = lane & 3;
    int wm = (warp >> 2) * 64, wn = (warp & 3) * 32;
    int m0 = blockIdx.y * 128, n0 = blockIdx.x * 128;

    const __half* Ab = A + (size_t)m0 * lda;
    const __half* Bb_ = Bm + (size_t)n0 * ldb;

    float acc[4][4][4];
    #pragma unroll
    for (int i = 0; i < 4; i++)
        #pragma unroll
        for (int j = 0; j < 4; j++)
            #pragma unroll
            for (int l = 0; l < 4; l++) acc[i][j][l] = 0.f;

    auto issue = [&](int kt, int st) {
        float* As = sm + st * STW;
        float* Bs = As + AWORDS;
        const __half* Ag = Ab + kt * 32;
        const __half* Bg = Bb_ + kt * 32;
        #pragma unroll
        for (int it = 0; it < 2; it++) {           // A: 128 rows x 32 halves = 512 x16B
            int c = t + it * 256;
            int r = c >> 2, c8 = (c & 3) * 8;      // 8 halves per chunk
            cp16((uint32_t)__cvta_generic_to_shared(As + r * AW + c8 / 2),
                 Ag + (size_t)r * lda + c8);
        }
        #pragma unroll
        for (int it = 0; it < 2; it++) {           // B: 128 rows x 32 halves
            int c = t + it * 256;
            int r = c >> 2, c8 = (c & 3) * 8;
            cp16((uint32_t)__cvta_generic_to_shared(Bs + r * BW + c8 / 2),
                 Bg + (size_t)r * ldb + c8);
        }
        CP_COMMIT();
    };

    auto compute = [&](int st) {
        const uint32_t* As = reinterpret_cast<const uint32_t*>(sm + st * STW);
        const uint32_t* Bs = As + AWORDS;
        #pragma unroll
        for (int ks = 0; ks < 2; ks++) {           // k16 per step
            int k0 = ks * 8;                       // word offset
            uint32_t af[4][4], bf[4][2];
            #pragma unroll
            for (int mt = 0; mt < 4; mt++) {
                int r = wm + mt * 16 + g;
                af[mt][0] = As[r * AW + k0 + tg];
                af[mt][1] = As[(r + 8) * AW + k0 + tg];
                af[mt][2] = As[r * AW + k0 + tg + 4];
                af[mt][3] = As[(r + 8) * AW + k0 + tg + 4];
            }
            #pragma unroll
            for (int nt = 0; nt < 4; nt++) {
                int c = wn + nt * 8 + g;
                bf[nt][0] = Bs[c * BW + k0 + tg];
                bf[nt][1] = Bs[c * BW + k0 + tg + 4];
            }
            #pragma unroll
            for (int mt = 0; mt < 4; mt++)
                #pragma unroll
                for (int nt = 0; nt < 4; nt++)
                    mma_f16(acc[mt][nt], af[mt], bf[nt]);
        }
    };

    const int KT = K / 32;
    issue(0, 0);
    issue(1, 1);

    for (int kt = 0; kt < KT; kt++) {
        if (kt + 1 < KT) { CP_WAIT(1); } else { CP_WAIT(0); }
        __syncthreads();
        compute(kt % 3);
        if (kt + 2 < KT) issue(kt + 2, (kt + 2) % 3);
    }

    // ---- epilogue ----
    #pragma unroll
    for (int mt = 0; mt < 4; mt++) {
        int r0 = m0 + wm + mt * 16 + g;
        #pragma unroll
        for (int nt = 0; nt < 4; nt++) {
            int c = n0 + wn + nt * 8 + 2 * tg;
            #pragma unroll
            for (int half_ = 0; half_ < 2; half_++) {
                int r = r0 + half_ * 8;
                float v0 = acc[mt][nt][half_ * 2 + 0];
                float v1 = acc[mt][nt][half_ * 2 + 1];
                v0 += bias[c]; v1 += bias[c + 1];
                if (GELU_ACT) {
                    v0 = 0.5f * v0 * (1.0f + erff(v0 * 0.70710678118654752f));
                    v1 = 0.5f * v1 * (1.0f + erff(v1 * 0.70710678118654752f));
                }
                if (HAS_RES) {
                    float2 rv = *reinterpret_cast<const float2*>(
                        resid + (size_t)r * ldc + c);
                    v0 += rv.x; v1 += rv.y;
                }
                if (OUT_HALF) {
                    __half2 hv = __floats2half2_rn(v0, v1);
                    *reinterpret_cast<__half2*>((__half*)Cm + (size_t)r * ldc + c) = hv;
                } else {
                    float2 ov; ov.x = v0; ov.y = v1;
                    *reinterpret_cast<float2*>((float*)Cm + (size_t)r * ldc + c) = ov;
                }
            }
        }
    }
}

// ---------------- fused flash attention (tf32 mma.sync; o stored half) ----------------
__global__ void __launch_bounds__(256) flash_kernel(
    const float* __restrict__ qkv, const float* __restrict__ kf,
    const float* __restrict__ vf, __half* __restrict__ o)
{
    extern __shared__ float fsm[];
    const int TW = 68;
    const int KWORDS = 64 * TW;

    int t = threadIdx.x, lane = t & 31, w = t >> 5;
    int g = lane >> 2, tg = lane & 3;
    int bh = blockIdx.y, b = bh >> 4, h = bh & 15;
    int q0 = blockIdx.x * 128;

    const float* Qg = qkv + ((size_t)(b * NPp + q0)) * C3 + h * HDd;
    #pragma unroll
    for (int it = 0; it < 8; it++) {
        int id = t + it * 256;
        int r = id >> 4, c4 = (id & 15) * 4;
        float4 v = *reinterpret_cast<const float4*>(Qg + (size_t)r * C3 + c4);
        float* d = fsm + r * TW + c4;
        d[0] = v.x; d[1] = v.y; d[2] = v.z; d[3] = v.w;
    }
    __syncthreads();

    uint32_t qf[8][4];
    {
        int r0 = w * 16 + g;
        #pragma unroll
        for (int kk = 0; kk < 8; kk++) {
            qf[kk][0] = f2tf32(fsm[r0 * TW + kk * 8 + tg] * 0.125f);
            qf[kk][1] = f2tf32(fsm[(r0 + 8) * TW + kk * 8 + tg] * 0.125f);
            qf[kk][2] = f2tf32(fsm[r0 * TW + kk * 8 + tg + 4] * 0.125f);
            qf[kk][3] = f2tf32(fsm[(r0 + 8) * TW + kk * 8 + tg + 4] * 0.125f);
        }
    }
    __syncthreads();

    const float* Kg = kf + (size_t)bh * Nn * HDd;
    const float* Vg = vf + (size_t)bh * Nn * HDd;

    auto issue_tile = [&](int j, int buf) {
        float* Ks = fsm + buf * (2 * KWORDS);
        float* Vs = Ks + KWORDS;
        const float* kg = Kg + (size_t)j * 64 * HDd;
        const float* vg = Vg + (size_t)j * 64 * HDd;
        #pragma unroll
        for (int it = 0; it < 4; it++) {
            int id = t + it * 256;
            int r = id >> 4, c4 = (id & 15) * 4;
            cp16((uint32_t)__cvta_generic_to_shared(Ks + r * TW + c4), kg + r * HDd + c4);
            cp16((uint32_t)__cvta_generic_to_shared(Vs + r * TW + c4), vg + r * HDd + c4);
        }
    };

    float m_r[2] = {-1e30f, -1e30f};
    float l_r[2] = {0.f, 0.f};
    float o_acc[8][4];
    #pragma unroll
    for (int i = 0; i < 8; i++)
        #pragma unroll
        for (int j = 0; j < 4; j++) o_acc[i][j] = 0.f;

    const unsigned FULL = 0xffffffffu;
    const int srcA = (lane & ~3) | (tg >> 1);
    const int srcB = srcA + 2;

    issue_tile(0, 0);
    CP_COMMIT();

    for (int j = 0; j < Nn / 64; j++) {
        int buf = j & 1;
        if (j + 1 < Nn / 64) { issue_tile(j + 1, buf ^ 1); CP_COMMIT(); CP_WAIT(1); }
        else                 { CP_WAIT(0); }
        __syncthreads();

        const uint32_t* Ku = reinterpret_cast<const uint32_t*>(fsm + buf * (2 * KWORDS));
        const uint32_t* Vu = Ku + KWORDS;

        float s[8][4];
        #pragma unroll
        for (int nt = 0; nt < 8; nt++)
            #pragma unroll
            for (int i = 0; i < 4; i++) s[nt][i] = 0.f;
        #pragma unroll
        for (int kk = 0; kk < 8; kk++) {
            #pragma unroll
            for (int nt = 0; nt < 8; nt++) {
                uint32_t bb[2];
                bb[0] = Ku[(nt * 8 + g) * TW + kk * 8 + tg];
                bb[1] = Ku[(nt * 8 + g) * TW + kk * 8 + tg + 4];
                mma_tf32(s[nt], qf[kk], bb);
            }
        }

        float mn0 = m_r[0], mn1 = m_r[1];
        #pragma unroll
        for (int nt = 0; nt < 8; nt++) {
            mn0 = fmaxf(mn0, fmaxf(s[nt][0], s[nt][1]));
            mn1 = fmaxf(mn1, fmaxf(s[nt][2], s[nt][3]));
        }
        mn0 = fmaxf(mn0, __shfl_xor_sync(FULL, mn0, 1));
        mn0 = fmaxf(mn0, __shfl_xor_sync(FULL, mn0, 2));
        mn1 = fmaxf(mn1, __shfl_xor_sync(FULL, mn1, 1));
        mn1 = fmaxf(mn1, __shfl_xor_sync(FULL, mn1, 2));
        float c0 = __expf(m_r[0] - mn0);
        float c1 = __expf(m_r[1] - mn1);
        m_r[0] = mn0; m_r[1] = mn1;

        float pf_[8][4];
        float rs0 = 0.f, rs1 = 0.f;
        #pragma unroll
        for (int nt = 0; nt < 8; nt++) {
            pf_[nt][0] = __expf(s[nt][0] - mn0);
            pf_[nt][1] = __expf(s[nt][1] - mn0);
            pf_[nt][2] = __expf(s[nt][2] - mn1);
            pf_[nt][3] = __expf(s[nt][3] - mn1);
            rs0 += pf_[nt][0] + pf_[nt][1];
            rs1 += pf_[nt][2] + pf_[nt][3];
        }
        rs0 += __shfl_xor_sync(FULL, rs0, 1); rs0 += __shfl_xor_sync(FULL, rs0, 2);
        rs1 += __shfl_xor_sync(FULL, rs1, 1); rs1 += __shfl_xor_sync(FULL, rs1, 2);
        l_r[0] = l_r[0] * c0 + rs0;
        l_r[1] = l_r[1] * c1 + rs1;
        #pragma unroll
        for (int nt = 0; nt < 8; nt++) {
            o_acc[nt][0] *= c0; o_acc[nt][1] *= c0;
            o_acc[nt][2] *= c1; o_acc[nt][3] *= c1;
        }

        #pragma unroll
        for (int kk2 = 0; kk2 < 8; kk2++) {
            float v0 = pf_[kk2][0], v1 = pf_[kk2][1], v2 = pf_[kk2][2], v3 = pf_[kk2][3];
            float w0 = __shfl_sync(FULL, v0, srcA), w1 = __shfl_sync(FULL, v1, srcA);
            float w2 = __shfl_sync(FULL, v2, srcA), w3 = __shfl_sync(FULL, v3, srcA);
            float y0 = __shfl_sync(FULL, v0, srcB), y1 = __shfl_sync(FULL, v1, srcB);
            float y2 = __shfl_sync(FULL, v2, srcB), y3 = __shfl_sync(FULL, v3, srcB);
            bool odd = (tg & 1);
            uint32_t af[4];
            af[0] = f2tf32(odd ? w1 : w0);
            af[1] = f2tf32(odd ? w3 : w2);
            af[2] = f2tf32(odd ? y1 : y0);
            af[3] = f2tf32(odd ? y3 : y2);
            #pragma unroll
            for (int nt2 = 0; nt2 < 8; nt2++) {
                uint32_t bb[2];
                bb[0] = Vu[(kk2 * 8 + tg) * TW + nt2 * 8 + g];
                bb[1] = Vu[(kk2 * 8 + tg + 4) * TW + nt2 * 8 + g];
                mma_tf32(o_acc[nt2], af, bb);
            }
        }
        __syncthreads();
    }

    float inv0 = 1.0f / l_r[0], inv1 = 1.0f / l_r[1];
    __half* Og = o + ((size_t)(b * NPp + q0 + w * 16 + g)) * Cc + h * HDd;
    #pragma unroll
    for (int nt2 = 0; nt2 < 8; nt2++) {
        int c = nt2 * 8 + 2 * tg;
        __half2 h0 = __floats2half2_rn(o_acc[nt2][0] * inv0, o_acc[nt2][1] * inv0);
        __half2 h1 = __floats2half2_rn(o_acc[nt2][2] * inv1, o_acc[nt2][3] * inv1);
        *reinterpret_cast<__half2*>(Og + c) = h0;
        *reinterpret_cast<__half2*>(Og + (size_t)8 * Cc + c) = h1;
    }
}

// ---------------- LayerNorm (half output) ----------------
__global__ void ln_kernel(const float* __restrict__ x, const float* __restrict__ g,
                          const float* __restrict__ b, __half* __restrict__ out)
{
    size_t row = blockIdx.x;
    const float* xr = x + row * Cc;
    __half* orow = out + row * Cc;
    int t = threadIdx.x;
    float4 v = reinterpret_cast<const float4*>(xr)[t];
    float s  = v.x + v.y + v.z + v.w;
    float ss = v.x*v.x + v.y*v.y + v.z*v.z + v.w*v.w;
    #pragma unroll
    for (int o = 16; o > 0; o >>= 1) {
        s  += __shfl_xor_sync(0xffffffffu, s,  o);
        ss += __shfl_xor_sync(0xffffffffu, ss, o);
    }
    __shared__ float r0[8], r1[8];
    if ((t & 31) == 0) { r0[t >> 5] = s; r1[t >> 5] = ss; }
    __syncthreads();
    s = 0.f; ss = 0.f;
    #pragma unroll
    for (int i = 0; i < 8; i++) { s += r0[i]; ss += r1[i]; }
    float mu  = s * (1.0f / Cc);
    float var = ss * (1.0f / Cc) - mu * mu;
    float inv = rsqrtf(var + 1e-5f);
    float4 gv = reinterpret_cast<const float4*>(g)[t];
    float4 bv = reinterpret_cast<const float4*>(b)[t];
    __half2 p0 = __floats2half2_rn((v.x - mu) * inv * gv.x + bv.x,
                                   (v.y - mu) * inv * gv.y + bv.y);
    __half2 p1 = __floats2half2_rn((v.z - mu) * inv * gv.z + bv.z,
                                   (v.w - mu) * inv * gv.w + bv.w);
    reinterpret_cast<__half2*>(orow)[2 * t]     = p0;
    reinterpret_cast<__half2*>(orow)[2 * t + 1] = p1;
}

// ---------------- mask scan: warp-parallel prefix scan ----------------
__global__ void p2t_kernel(const unsigned* __restrict__ mask)
{
    int b = blockIdx.x;
    int lane = threadIdx.x;
    const unsigned* mrow = mask + b * Nn;
    int base = lane * 32;
    unsigned bits = 0;
    int cnt = 0;
    #pragma unroll
    for (int i = 0; i < 32; i++) {
        unsigned mv = mrow[base + i] != 0u;
        bits |= mv << i;
        cnt += (int)mv;
    }
    int excl = cnt;
    #pragma unroll
    for (int o = 1; o < 32; o <<= 1) {
        int v = __shfl_up_sync(0xffffffffu, excl, o);
        if (lane >= o) excl += v;
    }
    excl -= cnt;
    int run = excl;
    #pragma unroll
    for (int i = 0; i < 32; i++) {
        bool mv = (bits >> i) & 1u;
        g_p2t[b * Nn + base + i] = mv ? run : -1;
        run += mv ? 1 : 0;
    }
}

// ---------------- KV fill (float4), pre-rounds to tf32 ----------------
__global__ void kvfill_kernel(const float4* __restrict__ ck, const float4* __restrict__ cv)
{
    size_t idx = (size_t)blockIdx.x * blockDim.x + threadIdx.x;
    int d4 = idx & 15;
    int n  = (idx >> 4) & (Nn - 1);
    int h  = (idx >> 14) & (Hh - 1);
    int b  = (int)(idx >> 18);
    int tok = g_p2t[b * Nn + n];
    float4 kv, vv;
    if (tok >= 0) {
        const float4* qkv4 = reinterpret_cast<const float4*>(g_qkv);
        size_t q = ((size_t)(b * NPp + tok)) * (C3 / 4) + (Cc / 4) + h * (HDd / 4) + d4;
        kv = qkv4[q];
        vv = qkv4[q + Cc / 4];
    } else {
        kv = ck[idx];
        vv = cv[idx];
    }
    kv.x = rnd32(kv.x); kv.y = rnd32(kv.y); kv.z = rnd32(kv.z); kv.w = rnd32(kv.w);
    vv.x = rnd32(vv.x); vv.y = rnd32(vv.y); vv.z = rnd32(vv.z); vv.w = rnd32(vv.w);
    reinterpret_cast<float4*>(g_kf)[idx] = kv;
    reinterpret_cast<float4*>(g_vf)[idx] = vv;
}

// ---------------- launch ----------------
extern "C" void kernel_launch(void* const* d_in, const int* in_sizes, int n_in,
                              void* d_out, int out_size)
{
    const float*    x      = (const float*)   d_in[0];
    const float*    cachek = (const float*)   d_in[1];
    const float*    cachev = (const float*)   d_in[2];
    const unsigned* mask   = (const unsigned*)d_in[3];
    const float*    qkv_w  = (const float*)   d_in[4];
    const float*    qkv_b  = (const float*)   d_in[5];
    const float*    proj_w = (const float*)   d_in[6];
    const float*    proj_b = (const float*)   d_in[7];
    const float*    n1_g   = (const float*)   d_in[8];
    const float*    n1_b   = (const float*)   d_in[9];
    const float*    n2_g   = (const float*)   d_in[10];
    const float*    n2_b   = (const float*)   d_in[11];
    const float*    fc1_w  = (const float*)   d_in[12];
    const float*    fc1_b  = (const float*)   d_in[13];
    const float*    fc2_w  = (const float*)   d_in[14];
    const float*    fc2_b  = (const float*)   d_in[15];
    float* out = (float*)d_out;

    __half *h, *o, *hid, *wq, *wp, *w1, *w2;
    float *qkv, *kf, *vf, *x1;
    cudaGetSymbolAddress((void**)&h,   g_h);
    cudaGetSymbolAddress((void**)&qkv, g_qkv);
    cudaGetSymbolAddress((void**)&kf,  g_kf);
    cudaGetSymbolAddress((void**)&vf,  g_vf);
    cudaGetSymbolAddress((void**)&o,   g_o);
    cudaGetSymbolAddress((void**)&x1,  g_x1);
    cudaGetSymbolAddress((void**)&hid, g_hid);
    cudaGetSymbolAddress((void**)&wq,  g_wq);
    cudaGetSymbolAddress((void**)&wp,  g_wp);
    cudaGetSymbolAddress((void**)&w1,  g_w1);
    cudaGetSymbolAddress((void**)&w2,  g_w2);

    const int GEMM_SMEM  = 3 * (128 * 20 + 128 * 20) * 4;   // 61440 B
    const int FLASH_SMEM = 2 * 2 * 64 * 68 * 4;             // 69632 B
    cudaFuncSetAttribute((const void*)mma_gemm<false, false, false>,
                         cudaFuncAttributeMaxDynamicSharedMemorySize, GEMM_SMEM);
    cudaFuncSetAttribute((const void*)mma_gemm<false, false, true>,
                         cudaFuncAttributeMaxDynamicSharedMemorySize, GEMM_SMEM);
    cudaFuncSetAttribute((const void*)mma_gemm<true, true, false>,
                         cudaFuncAttributeMaxDynamicSharedMemorySize, GEMM_SMEM);
    cudaFuncSetAttribute(flash_kernel,
                         cudaFuncAttributeMaxDynamicSharedMemorySize, FLASH_SMEM);

    // 0. pre-convert + transpose all weights to half [N][K]
    wtrans_kernel<<<12288, 256>>>(qkv_w, proj_w, fc1_w, fc2_w);

    // 1. LN1 -> half
    ln_kernel<<<Mtok, 256>>>(x, n1_g, n1_b, h);

    // 2. QKV = h @ wq^T + qkv_b  (float out)
    mma_gemm<false, false, false><<<dim3(C3 / 128, Mtok / 128), 256, GEMM_SMEM>>>(
        h, wq, qkv, Cc, Cc, Cc, C3, qkv_b, nullptr);

    // 3. mask scan
    p2t_kernel<<<Bb, 32>>>(mask);

    // 4. KV full fill (tf32-rounded float)
    kvfill_kernel<<<((Bb * Hh * Nn * HDd) / 4) / 256, 256>>>(
        (const float4*)cachek, (const float4*)cachev);

    // 5-7. fused attention (o -> half)
    flash_kernel<<<dim3(NPp / 128, Bb * Hh), 256, FLASH_SMEM>>>(qkv, kf, vf, o);

    // 8. x1 = x + o @ wp^T + proj_b  (float out)
    mma_gemm<false, false, true><<<dim3(Cc / 128, Mtok / 128), 256, GEMM_SMEM>>>(
        o, wp, x1, Cc, Cc, Cc, Cc, proj_b, x);

    // 9. LN2 -> half
    ln_kernel<<<Mtok, 256>>>(x1, n2_g, n2_b, h);

    // 10. hid = gelu(h @ w1^T + fc1_b)  (half out)
    mma_gemm<true, true, false><<<dim3(HIDh / 128, Mtok / 128), 256, GEMM_SMEM>>>(
        h, w1, hid, Cc, Cc, Cc, HIDh, fc1_b, nullptr);

    // 11. out = x1 + hid @ w2^T + fc2_b  (float out)
    mma_gemm<false, false, true><<<dim3(Cc / 128, Mtok / 128), 256, GEMM_SMEM>>>(
        hid, w2, out, HIDh, HIDh, HIDh, Cc, fc2_b, x1);
}

// round 14
// speedup vs baseline: 2.3685x; 1.1466x over previous
#include <cuda_runtime.h>
#include <cuda_fp16.h>
#include <math.h>
#include <stdint.h>

// Problem constants
#define Bb   16
#define NPp  512
#define Nn   1024
#define Cc   1024
#define Hh   16
#define HDd  64
#define C3   3072
#define HIDh 4096
#define Mtok 8192   // B*NP

// ---------------- scratch (device globals) ----------------
__device__ __half g_h  [(size_t)Mtok * Cc];          // LN out (half)
__device__ float  g_qkv[(size_t)Mtok * C3];          // QKV (float)
__device__ __half g_kf [(size_t)Bb * Hh * Nn * HDd]; // K full (half)
__device__ __half g_vf [(size_t)Bb * Hh * Nn * HDd]; // V full (half)
__device__ __half g_o  [(size_t)Mtok * Cc];          // attention out (half)
__device__ float  g_x1 [(size_t)Mtok * Cc];          // x + proj (float)
__device__ __half g_hid[(size_t)Mtok * HIDh];        // MLP hidden (half)
__device__ int    g_p2t[Bb * Nn];
// half, transposed [N][K] weights
__device__ __half g_wq [(size_t)C3 * Cc];
__device__ __half g_wp [(size_t)Cc * Cc];
__device__ __half g_w1 [(size_t)HIDh * Cc];
__device__ __half g_w2 [(size_t)Cc * HIDh];

// ---------------- helpers ----------------
__device__ __forceinline__ void mma_f16(float c[4], const uint32_t a[4], const uint32_t b[2]) {
    asm volatile(
        "mma.sync.aligned.m16n8k16.row.col.f32.f16.f16.f32 "
        "{%0,%1,%2,%3}, {%4,%5,%6,%7}, {%8,%9}, {%0,%1,%2,%3};"
        : "+f"(c[0]), "+f"(c[1]), "+f"(c[2]), "+f"(c[3])
        : "r"(a[0]), "r"(a[1]), "r"(a[2]), "r"(a[3]), "r"(b[0]), "r"(b[1]));
}
__device__ __forceinline__ uint32_t packh2(float a, float b) {
    __half2 h = __floats2half2_rn(a, b);
    return *reinterpret_cast<uint32_t*>(&h);
}
__device__ __forceinline__ void cp16(uint32_t saddr, const void* g) {
    asm volatile("cp.async.cg.shared.global [%0], [%1], 16;" :: "r"(saddr), "l"(g));
}
#define CP_COMMIT() asm volatile("cp.async.commit_group;")
#define CP_WAIT(n)  asm volatile("cp.async.wait_group %0;" :: "n"(n))

// ---------------- weight pre-round+transpose: float [K][N] -> half [N][K] ----------------
__global__ void wtrans_kernel(const float* __restrict__ wq, const float* __restrict__ wp,
                              const float* __restrict__ w1, const float* __restrict__ w2)
{
    __shared__ __half tile[32][33];
    int bid = blockIdx.x;
    const float* src; __half* dst; int K_, N_, tk, tn;
    if (bid < 3072)      { src = wq; dst = g_wq; K_ = Cc;   N_ = C3;   int id = bid;        tk = id / 96;  tn = id % 96; }
    else if (bid < 4096) { src = wp; dst = g_wp; K_ = Cc;   N_ = Cc;   int id = bid - 3072; tk = id / 32;  tn = id % 32; }
    else if (bid < 8192) { src = w1; dst = g_w1; K_ = Cc;   N_ = HIDh; int id = bid - 4096; tk = id / 128; tn = id % 128; }
    else                 { src = w2; dst = g_w2; K_ = HIDh; N_ = Cc;   int id = bid - 8192; tk = id / 32;  tn = id % 32; }
    int k0 = tk * 32, n0 = tn * 32;
    int t = threadIdx.x;
    #pragma unroll
    for (int it = 0; it < 4; it++) {
        int id = t + it * 256;
        int kk = id >> 5, nn = id & 31;
        tile[kk][nn] = __float2half_rn(src[(size_t)(k0 + kk) * N_ + n0 + nn]);
    }
    __syncthreads();
    #pragma unroll
    for (int it = 0; it < 4; it++) {
        int id = t + it * 256;
        int nn = id >> 5, kk = id & 31;
        dst[(size_t)(n0 + nn) * K_ + k0 + kk] = tile[kk][nn];
    }
}

// ---------------- fp16 mma.sync GEMM, cp.async 3-stage, BK=32 (R13 exact) ----------------
template<bool OUT_HALF, bool GELU_ACT, bool HAS_RES>
__global__ void __launch_bounds__(256) mma_gemm(
    const __half* __restrict__ A, const __half* __restrict__ Bm, void* __restrict__ Cm,
    int K, int lda, int ldb, int ldc,
    const float* __restrict__ bias, const float* __restrict__ resid)
{
    const int AW = 20, BW = 20;
    const int AWORDS = 128 * AW, BWORDS = 128 * BW;
    const int STW = AWORDS + BWORDS;

    extern __shared__ float sm[];

    int t = threadIdx.x, lane = t & 31, warp = t >> 5;
    int g = lane >> 2, tg = lane & 3;
    int wm = (warp >> 2) * 64, wn = (warp & 3) * 32;
    int m0 = blockIdx.y * 128, n0 = blockIdx.x * 128;

    const __half* Ab = A + (size_t)m0 * lda;
    const __half* Bb_ = Bm + (size_t)n0 * ldb;

    float acc[4][4][4];
    #pragma unroll
    for (int i = 0; i < 4; i++)
        #pragma unroll
        for (int j = 0; j < 4; j++)
            #pragma unroll
            for (int l = 0; l < 4; l++) acc[i][j][l] = 0.f;

    auto issue = [&](int kt, int st) {
        float* As = sm + st * STW;
        float* Bs = As + AWORDS;
        const __half* Ag = Ab + kt * 32;
        const __half* Bg = Bb_ + kt * 32;
        #pragma unroll
        for (int it = 0; it < 2; it++) {
            int c = t + it * 256;
            int r = c >> 2, c8 = (c & 3) * 8;
            cp16((uint32_t)__cvta_generic_to_shared(As + r * AW + c8 / 2),
                 Ag + (size_t)r * lda + c8);
        }
        #pragma unroll
        for (int it = 0; it < 2; it++) {
            int c = t + it * 256;
            int r = c >> 2, c8 = (c & 3) * 8;
            cp16((uint32_t)__cvta_generic_to_shared(Bs + r * BW + c8 / 2),
                 Bg + (size_t)r * ldb + c8);
        }
        CP_COMMIT();
    };

    auto compute = [&](int st) {
        const uint32_t* As = reinterpret_cast<const uint32_t*>(sm + st * STW);
        const uint32_t* Bs = As + AWORDS;
        #pragma unroll
        for (int ks = 0; ks < 2; ks++) {
            int k0 = ks * 8;
            uint32_t af[4][4], bf[4][2];
            #pragma unroll
            for (int mt = 0; mt < 4; mt++) {
                int r = wm + mt * 16 + g;
                af[mt][0] = As[r * AW + k0 + tg];
                af[mt][1] = As[(r + 8) * AW + k0 + tg];
                af[mt][2] = As[r * AW + k0 + tg + 4];
                af[mt][3] = As[(r + 8) * AW + k0 + tg + 4];
            }
            #pragma unroll
            for (int nt = 0; nt < 4; nt++) {
                int c = wn + nt * 8 + g;
                bf[nt][0] = Bs[c * BW + k0 + tg];
                bf[nt][1] = Bs[c * BW + k0 + tg + 4];
            }
            #pragma unroll
            for (int mt = 0; mt < 4; mt++)
                #pragma unroll
                for (int nt = 0; nt < 4; nt++)
                    mma_f16(acc[mt][nt], af[mt], bf[nt]);
        }
    };

    const int KT = K / 32;
    issue(0, 0);
    issue(1, 1);

    for (int kt = 0; kt < KT; kt++) {
        if (kt + 1 < KT) { CP_WAIT(1); } else { CP_WAIT(0); }
        __syncthreads();
        compute(kt % 3);
        if (kt + 2 < KT) issue(kt + 2, (kt + 2) % 3);
    }

    #pragma unroll
    for (int mt = 0; mt < 4; mt++) {
        int r0 = m0 + wm + mt * 16 + g;
        #pragma unroll
        for (int nt = 0; nt < 4; nt++) {
            int c = n0 + wn + nt * 8 + 2 * tg;
            #pragma unroll
            for (int half_ = 0; half_ < 2; half_++) {
                int r = r0 + half_ * 8;
                float v0 = acc[mt][nt][half_ * 2 + 0];
                float v1 = acc[mt][nt][half_ * 2 + 1];
                v0 += bias[c]; v1 += bias[c + 1];
                if (GELU_ACT) {
                    v0 = 0.5f * v0 * (1.0f + erff(v0 * 0.70710678118654752f));
                    v1 = 0.5f * v1 * (1.0f + erff(v1 * 0.70710678118654752f));
                }
                if (HAS_RES) {
                    float2 rv = *reinterpret_cast<const float2*>(
                        resid + (size_t)r * ldc + c);
                    v0 += rv.x; v1 += rv.y;
                }
                if (OUT_HALF) {
                    __half2 hv = __floats2half2_rn(v0, v1);
                    *reinterpret_cast<__half2*>((__half*)Cm + (size_t)r * ldc + c) = hv;
                } else {
                    float2 ov; ov.x = v0; ov.y = v1;
                    *reinterpret_cast<float2*>((float*)Cm + (size_t)r * ldc + c) = ov;
                }
            }
        }
    }
}

// ---------------- fused flash attention, fp16 mma ----------------
// K/V half in gmem. S = Qh Kh^T (f32 acc), online softmax, O += Ph Vh.
// P C-fragments ARE A-fragments for fp16 — no shuffles.
__global__ void __launch_bounds__(256) flash_kernel(
    const float* __restrict__ qkv, const __half* __restrict__ kf,
    const __half* __restrict__ vf, __half* __restrict__ o)
{
    extern __shared__ float fsm[];
    const int QW = 68;                       // Q staging stride (floats)
    const int KVH = 72;                      // K/V row stride (halves)
    const int KVHALVES = 64 * KVH;           // 4608 halves per matrix

    __half* hsm = reinterpret_cast<__half*>(fsm);

    int t = threadIdx.x, lane = t & 31, w = t >> 5;
    int g = lane >> 2, tg = lane & 3;
    int bh = blockIdx.y, b = bh >> 4, h = bh & 15;
    int q0 = blockIdx.x * 128;

    // ---- Q -> smem (float) ----
    const float* Qg = qkv + ((size_t)(b * NPp + q0)) * C3 + h * HDd;
    #pragma unroll
    for (int it = 0; it < 8; it++) {
        int id = t + it * 256;
        int r = id >> 4, c4 = (id & 15) * 4;
        float4 v = *reinterpret_cast<const float4*>(Qg + (size_t)r * C3 + c4);
        float* d = fsm + r * QW + c4;
        d[0] = v.x; d[1] = v.y; d[2] = v.z; d[3] = v.w;
    }
    __syncthreads();

    // ---- Q fragments: half2, scaled ----
    uint32_t qf[4][4];
    {
        int r0 = w * 16 + g;
        #pragma unroll
        for (int kc = 0; kc < 4; kc++) {
            int c0 = kc * 16 + 2 * tg;
            qf[kc][0] = packh2(fsm[r0 * QW + c0] * 0.125f,       fsm[r0 * QW + c0 + 1] * 0.125f);
            qf[kc][1] = packh2(fsm[(r0 + 8) * QW + c0] * 0.125f, fsm[(r0 + 8) * QW + c0 + 1] * 0.125f);
            qf[kc][2] = packh2(fsm[r0 * QW + c0 + 8] * 0.125f,   fsm[r0 * QW + c0 + 9] * 0.125f);
            qf[kc][3] = packh2(fsm[(r0 + 8) * QW + c0 + 8] * 0.125f, fsm[(r0 + 8) * QW + c0 + 9] * 0.125f);
        }
    }
    __syncthreads();

    const __half* Kg = kf + (size_t)bh * Nn * HDd;
    const __half* Vg = vf + (size_t)bh * Nn * HDd;

    auto issue_tile = [&](int j, int buf) {
        __half* Ks = hsm + buf * (2 * KVHALVES);
        __half* Vs = Ks + KVHALVES;
        const __half* kg = Kg + (size_t)j * 64 * HDd;
        const __half* vg = Vg + (size_t)j * 64 * HDd;
        #pragma unroll
        for (int it = 0; it < 2; it++) {
            int id = t + it * 256;               // 512 chunks of 16B per matrix
            int r = id >> 3, c8 = (id & 7) * 8;  // 8 halves per chunk
            cp16((uint32_t)__cvta_generic_to_shared(Ks + r * KVH + c8), kg + r * HDd + c8);
            cp16((uint32_t)__cvta_generic_to_shared(Vs + r * KVH + c8), vg + r * HDd + c8);
        }
    };

    float m_r[2] = {-1e30f, -1e30f};
    float l_r[2] = {0.f, 0.f};
    float o_acc[8][4];
    #pragma unroll
    for (int i = 0; i < 8; i++)
        #pragma unroll
        for (int j = 0; j < 4; j++) o_acc[i][j] = 0.f;

    const unsigned FULL = 0xffffffffu;

    issue_tile(0, 0);
    CP_COMMIT();

    for (int j = 0; j < Nn / 64; j++) {
        int buf = j & 1;
        if (j + 1 < Nn / 64) { issue_tile(j + 1, buf ^ 1); CP_COMMIT(); CP_WAIT(1); }
        else                 { CP_WAIT(0); }
        __syncthreads();

        const __half* Ks = hsm + buf * (2 * KVHALVES);
        const __half* Vs = Ks + KVHALVES;
        const uint32_t* K32 = reinterpret_cast<const uint32_t*>(Ks);

        // ---- S = Q K^T ----
        float s[8][4];
        #pragma unroll
        for (int nt = 0; nt < 8; nt++)
            #pragma unroll
            for (int i = 0; i < 4; i++) s[nt][i] = 0.f;
        #pragma unroll
        for (int kc = 0; kc < 4; kc++) {
            #pragma unroll
            for (int nt = 0; nt < 8; nt++) {
                int rowbase = (nt * 8 + g) * (KVH / 2) + kc * 8 + tg;
                uint32_t bb[2];
                bb[0] = K32[rowbase];
                bb[1] = K32[rowbase + 4];
                mma_f16(s[nt], qf[kc], bb);
            }
        }

        // ---- online softmax ----
        float mn0 = m_r[0], mn1 = m_r[1];
        #pragma unroll
        for (int nt = 0; nt < 8; nt++) {
            mn0 = fmaxf(mn0, fmaxf(s[nt][0], s[nt][1]));
            mn1 = fmaxf(mn1, fmaxf(s[nt][2], s[nt][3]));
        }
        mn0 = fmaxf(mn0, __shfl_xor_sync(FULL, mn0, 1));
        mn0 = fmaxf(mn0, __shfl_xor_sync(FULL, mn0, 2));
        mn1 = fmaxf(mn1, __shfl_xor_sync(FULL, mn1, 1));
        mn1 = fmaxf(mn1, __shfl_xor_sync(FULL, mn1, 2));
        float c0 = __expf(m_r[0] - mn0);
        float c1 = __expf(m_r[1] - mn1);
        m_r[0] = mn0; m_r[1] = mn1;

        float pf_[8][4];
        float rs0 = 0.f, rs1 = 0.f;
        #pragma unroll
        for (int nt = 0; nt < 8; nt++) {
            pf_[nt][0] = __expf(s[nt][0] - mn0);
            pf_[nt][1] = __expf(s[nt][1] - mn0);
            pf_[nt][2] = __expf(s[nt][2] - mn1);
            pf_[nt][3] = __expf(s[nt][3] - mn1);
            rs0 += pf_[nt][0] + pf_[nt][1];
            rs1 += pf_[nt][2] + pf_[nt][3];
        }
        rs0 += __shfl_xor_sync(FULL, rs0, 1); rs0 += __shfl_xor_sync(FULL, rs0, 2);
        rs1 += __shfl_xor_sync(FULL, rs1, 1); rs1 += __shfl_xor_sync(FULL, rs1, 2);
        l_r[0] = l_r[0] * c0 + rs0;
        l_r[1] = l_r[1] * c1 + rs1;
        #pragma unroll
        for (int nt = 0; nt < 8; nt++) {
            o_acc[nt][0] *= c0; o_acc[nt][1] *= c0;
            o_acc[nt][2] *= c1; o_acc[nt][3] *= c1;
        }

        // ---- O += P V : P C-frags ARE fp16 A-frags ----
        #pragma unroll
        for (int kc = 0; kc < 4; kc++) {
            uint32_t af[4];
            af[0] = packh2(pf_[2 * kc][0],     pf_[2 * kc][1]);
            af[1] = packh2(pf_[2 * kc][2],     pf_[2 * kc][3]);
            af[2] = packh2(pf_[2 * kc + 1][0], pf_[2 * kc + 1][1]);
            af[3] = packh2(pf_[2 * kc + 1][2], pf_[2 * kc + 1][3]);
            int kr0 = kc * 16 + 2 * tg;
            #pragma unroll
            for (int nt2 = 0; nt2 < 8; nt2++) {
                int c = nt2 * 8 + g;
                uint32_t bb[2];
                {
                    __half2 hv = __halves2half2(Vs[kr0 * KVH + c], Vs[(kr0 + 1) * KVH + c]);
                    bb[0] = *reinterpret_cast<uint32_t*>(&hv);
                }
                {
                    __half2 hv = __halves2half2(Vs[(kr0 + 8) * KVH + c], Vs[(kr0 + 9) * KVH + c]);
                    bb[1] = *reinterpret_cast<uint32_t*>(&hv);
                }
                mma_f16(o_acc[nt2], af, bb);
            }
        }
        __syncthreads();
    }

    float inv0 = 1.0f / l_r[0], inv1 = 1.0f / l_r[1];
    __half* Og = o + ((size_t)(b * NPp + q0 + w * 16 + g)) * Cc + h * HDd;
    #pragma unroll
    for (int nt2 = 0; nt2 < 8; nt2++) {
        int c = nt2 * 8 + 2 * tg;
        __half2 h0 = __floats2half2_rn(o_acc[nt2][0] * inv0, o_acc[nt2][1] * inv0);
        __half2 h1 = __floats2half2_rn(o_acc[nt2][2] * inv1, o_acc[nt2][3] * inv1);
        *reinterpret_cast<__half2*>(Og + c) = h0;
        *reinterpret_cast<__half2*>(Og + (size_t)8 * Cc + c) = h1;
    }
}

// ---------------- LayerNorm (half output) ----------------
__global__ void ln_kernel(const float* __restrict__ x, const float* __restrict__ g,
                          const float* __restrict__ b, __half* __restrict__ out)
{
    size_t row = blockIdx.x;
    const float* xr = x + row * Cc;
    __half* orow = out + row * Cc;
    int t = threadIdx.x;
    float4 v = reinterpret_cast<const float4*>(xr)[t];
    float s  = v.x + v.y + v.z + v.w;
    float ss = v.x*v.x + v.y*v.y + v.z*v.z + v.w*v.w;
    #pragma unroll
    for (int o = 16; o > 0; o >>= 1) {
        s  += __shfl_xor_sync(0xffffffffu, s,  o);
        ss += __shfl_xor_sync(0xffffffffu, ss, o);
    }
    __shared__ float r0[8], r1[8];
    if ((t & 31) == 0) { r0[t >> 5] = s; r1[t >> 5] = ss; }
    __syncthreads();
    s = 0.f; ss = 0.f;
    #pragma unroll
    for (int i = 0; i < 8; i++) { s += r0[i]; ss += r1[i]; }
    float mu  = s * (1.0f / Cc);
    float var = ss * (1.0f / Cc) - mu * mu;
    float inv = rsqrtf(var + 1e-5f);
    float4 gv = reinterpret_cast<const float4*>(g)[t];
    float4 bv = reinterpret_cast<const float4*>(b)[t];
    __half2 p0 = __floats2half2_rn((v.x - mu) * inv * gv.x + bv.x,
                                   (v.y - mu) * inv * gv.y + bv.y);
    __half2 p1 = __floats2half2_rn((v.z - mu) * inv * gv.z + bv.z,
                                   (v.w - mu) * inv * gv.w + bv.w);
    reinterpret_cast<__half2*>(orow)[2 * t]     = p0;
    reinterpret_cast<__half2*>(orow)[2 * t + 1] = p1;
}

// ---------------- mask scan: warp-parallel prefix scan ----------------
__global__ void p2t_kernel(const unsigned* __restrict__ mask)
{
    int b = blockIdx.x;
    int lane = threadIdx.x;
    const unsigned* mrow = mask + b * Nn;
    int base = lane * 32;
    unsigned bits = 0;
    int cnt = 0;
    #pragma unroll
    for (int i = 0; i < 32; i++) {
        unsigned mv = mrow[base + i] != 0u;
        bits |= mv << i;
        cnt += (int)mv;
    }
    int excl = cnt;
    #pragma unroll
    for (int o = 1; o < 32; o <<= 1) {
        int v = __shfl_up_sync(0xffffffffu, excl, o);
        if (lane >= o) excl += v;
    }
    excl -= cnt;
    int run = excl;
    #pragma unroll
    for (int i = 0; i < 32; i++) {
        bool mv = (bits >> i) & 1u;
        g_p2t[b * Nn + base + i] = mv ? run : -1;
        run += mv ? 1 : 0;
    }
}

// ---------------- KV fill: writes half ----------------
__global__ void kvfill_kernel(const float4* __restrict__ ck, const float4* __restrict__ cv)
{
    size_t idx = (size_t)blockIdx.x * blockDim.x + threadIdx.x;   // 4M groups of 4 elems
    int d4 = idx & 15;
    int n  = (idx >> 4) & (Nn - 1);
    int h  = (idx >> 14) & (Hh - 1);
    int b  = (int)(idx >> 18);
    int tok = g_p2t[b * Nn + n];
    float4 kv, vv;
    if (tok >= 0) {
        const float4* qkv4 = reinterpret_cast<const float4*>(g_qkv);
        size_t q = ((size_t)(b * NPp + tok)) * (C3 / 4) + (Cc / 4) + h * (HDd / 4) + d4;
        kv = qkv4[q];
        vv = qkv4[q + Cc / 4];
    } else {
        kv = ck[idx];
        vv = cv[idx];
    }
    uint2 kw, vw;
    kw.x = packh2(kv.x, kv.y); kw.y = packh2(kv.z, kv.w);
    vw.x = packh2(vv.x, vv.y); vw.y = packh2(vv.z, vv.w);
    reinterpret_cast<uint2*>(g_kf)[idx] = kw;
    reinterpret_cast<uint2*>(g_vf)[idx] = vw;
}

// ---------------- launch ----------------
extern "C" void kernel_launch(void* const* d_in, const int* in_sizes, int n_in,
                              void* d_out, int out_size)
{
    const float*    x      = (const float*)   d_in[0];
    const float*    cachek = (const float*)   d_in[1];
    const float*    cachev = (const float*)   d_in[2];
    const unsigned* mask   = (const unsigned*)d_in[3];
    const float*    qkv_w  = (const float*)   d_in[4];
    const float*    qkv_b  = (const float*)   d_in[5];
    const float*    proj_w = (const float*)   d_in[6];
    const float*    proj_b = (const float*)   d_in[7];
    const float*    n1_g   = (const float*)   d_in[8];
    const float*    n1_b   = (const float*)   d_in[9];
    const float*    n2_g   = (const float*)   d_in[10];
    const float*    n2_b   = (const float*)   d_in[11];
    const float*    fc1_w  = (const float*)   d_in[12];
    const float*    fc1_b  = (const float*)   d_in[13];
    const float*    fc2_w  = (const float*)   d_in[14];
    const float*    fc2_b  = (const float*)   d_in[15];
    float* out = (float*)d_out;

    __half *h, *o, *hid, *wq, *wp, *w1, *w2, *kf, *vf;
    float *qkv, *x1;
    cudaGetSymbolAddress((void**)&h,   g_h);
    cudaGetSymbolAddress((void**)&qkv, g_qkv);
    cudaGetSymbolAddress((void**)&kf,  g_kf);
    cudaGetSymbolAddress((void**)&vf,  g_vf);
    cudaGetSymbolAddress((void**)&o,   g_o);
    cudaGetSymbolAddress((void**)&x1,  g_x1);
    cudaGetSymbolAddress((void**)&hid, g_hid);
    cudaGetSymbolAddress((void**)&wq,  g_wq);
    cudaGetSymbolAddress((void**)&wp,  g_wp);
    cudaGetSymbolAddress((void**)&w1,  g_w1);
    cudaGetSymbolAddress((void**)&w2,  g_w2);

    const int GEMM_SMEM  = 3 * (128 * 20 + 128 * 20) * 4;          // 61440 B
    const int FLASH_SMEM = (2 * 2 * 64 * 72 * 2 > 128 * 68 * 4)
                           ? 2 * 2 * 64 * 72 * 2 : 128 * 68 * 4;   // 36864 B
    cudaFuncSetAttribute((const void*)mma_gemm<false, false, false>,
                         cudaFuncAttributeMaxDynamicSharedMemorySize, GEMM_SMEM);
    cudaFuncSetAttribute((const void*)mma_gemm<false, false, true>,
                         cudaFuncAttributeMaxDynamicSharedMemorySize, GEMM_SMEM);
    cudaFuncSetAttribute((const void*)mma_gemm<true, true, false>,
                         cudaFuncAttributeMaxDynamicSharedMemorySize, GEMM_SMEM);
    cudaFuncSetAttribute(flash_kernel,
                         cudaFuncAttributeMaxDynamicSharedMemorySize, FLASH_SMEM);

    // 0. pre-convert + transpose all weights to half [N][K]
    wtrans_kernel<<<12288, 256>>>(qkv_w, proj_w, fc1_w, fc2_w);

    // 1. LN1 -> half
    ln_kernel<<<Mtok, 256>>>(x, n1_g, n1_b, h);

    // 2. QKV = h @ wq^T + qkv_b  (float out)
    mma_gemm<false, false, false><<<dim3(C3 / 128, Mtok / 128), 256, GEMM_SMEM>>>(
        h, wq, qkv, Cc, Cc, Cc, C3, qkv_b, nullptr);

    // 3. mask scan
    p2t_kernel<<<Bb, 32>>>(mask);

    // 4. KV full fill (half out)
    kvfill_kernel<<<((Bb * Hh * Nn * HDd) / 4) / 256, 256>>>(
        (const float4*)cachek, (const float4*)cachev);

    // 5-7. fused attention (fp16 mma, o -> half)
    flash_kernel<<<dim3(NPp / 128, Bb * Hh), 256, FLASH_SMEM>>>(qkv, kf, vf, o);

    // 8. x1 = x + o @ wp^T + proj_b  (float out)
    mma_gemm<false, false, true><<<dim3(Cc / 128, Mtok / 128), 256, GEMM_SMEM>>>(
        o, wp, x1, Cc, Cc, Cc, Cc, proj_b, x);

    // 9. LN2 -> half
    ln_kernel<<<Mtok, 256>>>(x1, n2_g, n2_b, h);

    // 10. hid = gelu(h @ w1^T + fc1_b)  (half out)
    mma_gemm<true, true, false><<<dim3(HIDh / 128, Mtok / 128), 256, GEMM_SMEM>>>(
        h, w1, hid, Cc, Cc, Cc, HIDh, fc1_b, nullptr);

    // 11. out = x1 + hid @ w2^T + fc2_b  (float out)
    mma_gemm<false, false, true><<<dim3(Cc / 128, Mtok / 128), 256, GEMM_SMEM>>>(
        hid, w2, out, HIDh, HIDh, HIDh, Cc, fc2_b, x1);
}